// round 1
// baseline (speedup 1.0000x reference)
#include <cuda_runtime.h>

// ---------------------------------------------------------------------------
// GemNetTDecoder: full GNN forward.
// Input order (setup_inputs dict order):
//  0 z[256,256] 1 frac[16384,3] 2 lengths[256,3] 3 angles[256,3]
//  4 atom_types[16384] i32  5 src[327680] i32  6 dst[327680] i32
//  7 emb_table[101,128] 8 W_in[384,128] 9 b_in[128] 10 W_edge[384,128] 11 b_edge[128]
// 12 Wb_rbf[3,128,128] 13 Wb_msg[3,128,128] 14 bb_msg[3,128]
// 15 Wb_atom[3,128,128] 16 bb_atom[3,128] 17 Wb_upd[3,384,128] 18 bb_upd[3,128]
// 19 W_force[128,1] 20 b_force[1] 21 W_fc1[128,128] 22 b_fc1[128]
// 23 W_fc2[128,128] 24 b_fc2[128] 25 W_fc3[128,2] 26 b_fc3[2]
// Output: [16384*3] pred_cart_coord_diff then [16384*2] pred_atom_types (fp32)
// ---------------------------------------------------------------------------

#define PI_F 3.14159265358979323846f

constexpr int NCRYST = 256;
constexpr int AA     = 64;
constexpr int KNB    = 20;
constexpr int HIDC   = 128;
constexpr int LATC   = 256;
constexpr int NATOMS = NCRYST * AA;       // 16384
constexpr int NEDGE  = NATOMS * KNB;      // 327680
constexpr float FCUT = 6.0f;
constexpr float DELTA = FCUT / 127.0f;

constexpr size_t EH = (size_t)NEDGE * HIDC;   // 41,943,040

// Scratch (device globals; no allocations allowed)
__device__ float g_lat[NCRYST * 9];
__device__ float g_cart[NATOMS * 3];
__device__ float g_dist[NEDGE];
__device__ float g_env[NEDGE];
__device__ float g_unit[NEDGE * 3];
__device__ float g_rbf[EH];
__device__ float g_h[NATOMS * HIDC];
__device__ float g_m[EH];
__device__ float g_gate[EH];
__device__ float g_msg[EH];
__device__ float g_agg[NATOMS * HIDC];
__device__ float g_a1[NATOMS * HIDC];
__device__ float g_a2[NATOMS * HIDC];

// ---------------------------------------------------------------------------
__global__ void lattice_k(const float* __restrict__ lengths,
                          const float* __restrict__ angles) {
    int i = threadIdx.x;
    if (i >= NCRYST) return;
    float r0 = angles[i * 3 + 0] * (PI_F / 180.f);
    float r1 = angles[i * 3 + 1] * (PI_F / 180.f);
    float r2 = angles[i * 3 + 2] * (PI_F / 180.f);
    float c0 = cosf(r0), c1 = cosf(r1), c2 = cosf(r2), sg = sinf(r2);
    float a = lengths[i * 3 + 0], b = lengths[i * 3 + 1], c = lengths[i * 3 + 2];
    float cx = c * c1;
    float cy = c * (c0 - c1 * c2) / sg;
    float cz = sqrtf(fmaxf(c * c - cx * cx - cy * cy, 1e-8f));
    float* L = &g_lat[i * 9];
    L[0] = a;      L[1] = 0.f;    L[2] = 0.f;
    L[3] = b * c2; L[4] = b * sg; L[5] = 0.f;
    L[6] = cx;     L[7] = cy;     L[8] = cz;
}

__global__ void cart_k(const float* __restrict__ frac) {
    int i = blockIdx.x * blockDim.x + threadIdx.x;
    if (i >= NATOMS) return;
    const float* L = &g_lat[(i >> 6) * 9];
    float f0 = frac[i * 3 + 0], f1 = frac[i * 3 + 1], f2 = frac[i * 3 + 2];
    g_cart[i * 3 + 0] = f0 * L[0] + f1 * L[3] + f2 * L[6];
    g_cart[i * 3 + 1] = f0 * L[1] + f1 * L[4] + f2 * L[7];
    g_cart[i * 3 + 2] = f0 * L[2] + f1 * L[5] + f2 * L[8];
}

__global__ void edge_k(const int* __restrict__ src, const int* __restrict__ dst) {
    int e = blockIdx.x * blockDim.x + threadIdx.x;
    if (e >= NEDGE) return;
    int s = src[e], d = dst[e];
    float dx = g_cart[d * 3 + 0] - g_cart[s * 3 + 0];
    float dy = g_cart[d * 3 + 1] - g_cart[s * 3 + 1];
    float dz = g_cart[d * 3 + 2] - g_cart[s * 3 + 2];
    float dist = sqrtf(dx * dx + dy * dy + dz * dz + 1e-12f);
    g_dist[e] = dist;
    float inv = 1.f / dist;
    g_unit[e * 3 + 0] = dx * inv;
    g_unit[e * 3 + 1] = dy * inv;
    g_unit[e * 3 + 2] = dz * inv;
    g_env[e] = 0.5f * (cosf(PI_F * fminf(dist * (1.f / FCUT), 1.f)) + 1.f);
}

__global__ void rbf_k() {
    int e = blockIdx.x * 2 + (threadIdx.x >> 7);
    int k = threadIdx.x & 127;
    float t = g_dist[e] * (1.f / DELTA) - (float)k;
    g_rbf[(size_t)e * 128 + k] = __expf(-t * t) * g_env[e];
}

// ---------------------------------------------------------------------------
// Generic tiled GEMM: out[rows,128] = epilogue( X[rows,KDIM] @ W[KDIM,128] )
// MODE: 0 plain X ; 1 concat(emb[atype], z[batch]) ; 2 concat(h[src],h[dst],rbf)
//       3 concat(h[src],h[dst],m)
// EPI : 0 store raw ; 1 relu(acc+bias) ; 2 relu(acc+bias)*gate ;
//       3 base + relu(acc+bias)
// BM=64 BN=128 BK=16, 256 threads, 4x8 register tile.
// ---------------------------------------------------------------------------
template <int MODE, int KDIM, int EPI>
__global__ __launch_bounds__(256) void gemm_k(
    const float* __restrict__ X, const float* __restrict__ W,
    const float* __restrict__ bias, const float* __restrict__ gate,
    const float* __restrict__ base, float* __restrict__ out,
    const float* __restrict__ emb, const float* __restrict__ z,
    const int* __restrict__ atype, const int* __restrict__ srcp,
    const int* __restrict__ dstp) {
    __shared__ float Xs[16][68];
    __shared__ float Ws[16][128];
    __shared__ int ssrc[64], sdst[64], sat[64];

    int row0 = blockIdx.x * 64;
    int tid = threadIdx.x;
    if (MODE == 1) {
        if (tid < 64) sat[tid] = atype[row0 + tid];
        __syncthreads();
    }
    if (MODE >= 2) {
        if (tid < 64) { ssrc[tid] = srcp[row0 + tid]; sdst[tid] = dstp[row0 + tid]; }
        __syncthreads();
    }

    int c0 = (tid & 15) * 8;
    int r0 = (tid >> 4) * 4;
    float acc[4][8];
#pragma unroll
    for (int i = 0; i < 4; i++)
#pragma unroll
        for (int j = 0; j < 8; j++) acc[i][j] = 0.f;

    for (int k0 = 0; k0 < KDIM; k0 += 16) {
#pragma unroll
        for (int t = 0; t < 4; t++) {
            int lin = tid * 4 + t;
            int r = lin >> 4, kk = lin & 15;
            int k = k0 + kk;
            float v;
            if (MODE == 0) {
                v = X[(size_t)(row0 + r) * KDIM + k];
            } else if (MODE == 1) {
                v = (k < 128) ? emb[sat[r] * 128 + k]
                              : z[(size_t)((row0 + r) >> 6) * LATC + (k - 128)];
            } else {
                if (k < 128)      v = g_h[(size_t)ssrc[r] * 128 + k];
                else if (k < 256) v = g_h[(size_t)sdst[r] * 128 + (k - 128)];
                else if (MODE == 2) v = g_rbf[(size_t)(row0 + r) * 128 + (k - 256)];
                else              v = g_m[(size_t)(row0 + r) * 128 + (k - 256)];
            }
            Xs[kk][r] = v;
        }
#pragma unroll
        for (int t = 0; t < 2; t++) {
            int i4 = tid + t * 256;
            int kk = i4 >> 5, n = (i4 & 31) * 4;
            *(float4*)&Ws[kk][n] = *(const float4*)&W[(size_t)(k0 + kk) * 128 + n];
        }
        __syncthreads();
#pragma unroll
        for (int kk = 0; kk < 16; kk++) {
            float4 a  = *(const float4*)&Xs[kk][r0];
            float4 b0 = *(const float4*)&Ws[kk][c0];
            float4 b1 = *(const float4*)&Ws[kk][c0 + 4];
            float av[4] = {a.x, a.y, a.z, a.w};
            float bv[8] = {b0.x, b0.y, b0.z, b0.w, b1.x, b1.y, b1.z, b1.w};
#pragma unroll
            for (int i = 0; i < 4; i++)
#pragma unroll
                for (int j = 0; j < 8; j++) acc[i][j] += av[i] * bv[j];
        }
        __syncthreads();
    }

    float bv[8];
    if (EPI >= 1) {
        float4 q0 = *(const float4*)&bias[c0];
        float4 q1 = *(const float4*)&bias[c0 + 4];
        bv[0] = q0.x; bv[1] = q0.y; bv[2] = q0.z; bv[3] = q0.w;
        bv[4] = q1.x; bv[5] = q1.y; bv[6] = q1.z; bv[7] = q1.w;
    }
#pragma unroll
    for (int i = 0; i < 4; i++) {
        size_t off = (size_t)(row0 + r0 + i) * 128 + c0;
        float v[8];
#pragma unroll
        for (int j = 0; j < 8; j++) {
            float t = acc[i][j];
            if (EPI >= 1) t = fmaxf(t + bv[j], 0.f);
            v[j] = t;
        }
        if (EPI == 2) {
            float4 gg0 = *(const float4*)&gate[off];
            float4 gg1 = *(const float4*)&gate[off + 4];
            v[0] *= gg0.x; v[1] *= gg0.y; v[2] *= gg0.z; v[3] *= gg0.w;
            v[4] *= gg1.x; v[5] *= gg1.y; v[6] *= gg1.z; v[7] *= gg1.w;
        }
        if (EPI == 3) {
            float4 bb0 = *(const float4*)&base[off];
            float4 bb1 = *(const float4*)&base[off + 4];
            v[0] += bb0.x; v[1] += bb0.y; v[2] += bb0.z; v[3] += bb0.w;
            v[4] += bb1.x; v[5] += bb1.y; v[6] += bb1.z; v[7] += bb1.w;
        }
        float4 o0 = {v[0], v[1], v[2], v[3]};
        float4 o1 = {v[4], v[5], v[6], v[7]};
        *(float4*)&out[off] = o0;
        *(float4*)&out[off + 4] = o1;
    }
}

// ---------------------------------------------------------------------------
// Per-crystal segment sum of msg over dst -> g_agg.
// Crystal c owns edges [c*1280, (c+1)*1280) with dst inside [c*64, c*64+64).
// ---------------------------------------------------------------------------
__global__ __launch_bounds__(512) void segsum_k(const int* __restrict__ dst) {
    __shared__ float sagg[AA * HIDC];  // 32KB
    int c = blockIdx.x, tid = threadIdx.x;
    for (int i = tid; i < AA * HIDC; i += 512) sagg[i] = 0.f;
    __syncthreads();
    int col = tid & 127, grp = tid >> 7;
    int ebase = c * AA * KNB;
    for (int b = grp; b < AA * KNB; b += 4) {
        int e = ebase + b;
        int ld = dst[e] - (c << 6);
        atomicAdd(&sagg[ld * 128 + col], g_msg[(size_t)e * 128 + col]);
    }
    __syncthreads();
    for (int i = tid; i < AA * HIDC; i += 512)
        g_agg[(size_t)c * AA * HIDC + i] = sagg[i];
}

// ---------------------------------------------------------------------------
// f = m @ W_force + b ; out1[atom] = segsum(f * unit) per crystal.
// ---------------------------------------------------------------------------
__global__ __launch_bounds__(256) void force_k(const float* __restrict__ Wf,
                                               const float* __restrict__ bf,
                                               const int* __restrict__ dst,
                                               float* __restrict__ out) {
    __shared__ float sW[128];
    __shared__ float sacc[AA * 3];
    int c = blockIdx.x, tid = threadIdx.x;
    if (tid < 128) sW[tid] = Wf[tid];
    if (tid < AA * 3) sacc[tid] = 0.f;
    __syncthreads();
    int w = tid >> 5, lane = tid & 31;
    float b0 = bf[0];
    for (int el = w; el < AA * KNB; el += 8) {
        int e = c * AA * KNB + el;
        const float* mr = &g_m[(size_t)e * 128];
        float p = 0.f;
#pragma unroll
        for (int k = lane; k < 128; k += 32) p += mr[k] * sW[k];
#pragma unroll
        for (int o = 16; o; o >>= 1) p += __shfl_xor_sync(0xffffffffu, p, o);
        float f = p + b0;
        int ld = dst[e] - (c << 6);
        if (lane < 3) atomicAdd(&sacc[ld * 3 + lane], f * g_unit[e * 3 + lane]);
    }
    __syncthreads();
    if (tid < AA * 3) out[(size_t)c * AA * 3 + tid] = sacc[tid];
}

// Final fc3: 128 -> 2, one warp per atom.
__global__ __launch_bounds__(256) void fc3_k(const float* __restrict__ W,
                                             const float* __restrict__ b,
                                             float* __restrict__ out) {
    int atom = blockIdx.x * 8 + (threadIdx.x >> 5);
    int lane = threadIdx.x & 31;
    const float* ar = &g_a2[(size_t)atom * 128];
    float p0 = 0.f, p1 = 0.f;
#pragma unroll
    for (int k = lane; k < 128; k += 32) {
        float v = ar[k];
        p0 += v * W[k * 2 + 0];
        p1 += v * W[k * 2 + 1];
    }
#pragma unroll
    for (int o = 16; o; o >>= 1) {
        p0 += __shfl_xor_sync(0xffffffffu, p0, o);
        p1 += __shfl_xor_sync(0xffffffffu, p1, o);
    }
    if (lane == 0) {
        out[atom * 2 + 0] = p0 + b[0];
        out[atom * 2 + 1] = p1 + b[1];
    }
}

// ---------------------------------------------------------------------------
extern "C" void kernel_launch(void* const* d_in, const int* in_sizes, int n_in,
                              void* d_out, int out_size) {
    const float* z        = (const float*)d_in[0];
    const float* frac     = (const float*)d_in[1];
    const float* lengths  = (const float*)d_in[2];
    const float* angles   = (const float*)d_in[3];
    const int*   atype    = (const int*)d_in[4];
    const int*   src      = (const int*)d_in[5];
    const int*   dst      = (const int*)d_in[6];
    const float* emb      = (const float*)d_in[7];
    const float* W_in     = (const float*)d_in[8];
    const float* b_in     = (const float*)d_in[9];
    const float* W_edge   = (const float*)d_in[10];
    const float* b_edge   = (const float*)d_in[11];
    const float* Wb_rbf   = (const float*)d_in[12];
    const float* Wb_msg   = (const float*)d_in[13];
    const float* bb_msg   = (const float*)d_in[14];
    const float* Wb_atom  = (const float*)d_in[15];
    const float* bb_atom  = (const float*)d_in[16];
    const float* Wb_upd   = (const float*)d_in[17];
    const float* bb_upd   = (const float*)d_in[18];
    const float* W_force  = (const float*)d_in[19];
    const float* b_force  = (const float*)d_in[20];
    const float* W_fc1    = (const float*)d_in[21];
    const float* b_fc1    = (const float*)d_in[22];
    const float* W_fc2    = (const float*)d_in[23];
    const float* b_fc2    = (const float*)d_in[24];
    const float* W_fc3    = (const float*)d_in[25];
    const float* b_fc3    = (const float*)d_in[26];
    float* out = (float*)d_out;

    float *pRbf, *pH, *pM, *pGate, *pMsg, *pAgg, *pA1, *pA2;
    cudaGetSymbolAddress((void**)&pRbf,  g_rbf);
    cudaGetSymbolAddress((void**)&pH,    g_h);
    cudaGetSymbolAddress((void**)&pM,    g_m);
    cudaGetSymbolAddress((void**)&pGate, g_gate);
    cudaGetSymbolAddress((void**)&pMsg,  g_msg);
    cudaGetSymbolAddress((void**)&pAgg,  g_agg);
    cudaGetSymbolAddress((void**)&pA1,   g_a1);
    cudaGetSymbolAddress((void**)&pA2,   g_a2);

    // Geometry
    lattice_k<<<1, 256>>>(lengths, angles);
    cart_k<<<NATOMS / 256, 256>>>(frac);
    edge_k<<<NEDGE / 256, 256>>>(src, dst);
    rbf_k<<<NEDGE / 2, 256>>>();

    // h = relu(concat(emb, z) @ W_in + b_in)
    gemm_k<1, 384, 1><<<NATOMS / 64, 256>>>(nullptr, W_in, b_in, nullptr, nullptr,
                                            pH, emb, z, atype, src, dst);
    // m = relu(concat(h[src], h[dst], rbf) @ W_edge + b_edge)
    gemm_k<2, 384, 1><<<NEDGE / 64, 256>>>(nullptr, W_edge, b_edge, nullptr, nullptr,
                                           pM, emb, z, atype, src, dst);

    for (int i = 0; i < 3; i++) {
        // gate = rbf @ Wb_rbf[i]
        gemm_k<0, 128, 0><<<NEDGE / 64, 256>>>(pRbf, Wb_rbf + (size_t)i * 16384,
                                               nullptr, nullptr, nullptr, pGate,
                                               emb, z, atype, src, dst);
        // msg = relu(m @ Wb_msg[i] + bb_msg[i]) * gate
        gemm_k<0, 128, 2><<<NEDGE / 64, 256>>>(pM, Wb_msg + (size_t)i * 16384,
                                               bb_msg + i * 128, pGate, nullptr,
                                               pMsg, emb, z, atype, src, dst);
        // agg = segment_sum(msg, dst)
        segsum_k<<<NCRYST, 512>>>(dst);
        // h = h + relu(agg @ Wb_atom[i] + bb_atom[i])
        gemm_k<0, 128, 3><<<NATOMS / 64, 256>>>(pAgg, Wb_atom + (size_t)i * 16384,
                                                bb_atom + i * 128, nullptr, pH, pH,
                                                emb, z, atype, src, dst);
        // m = m + relu(concat(h[src], h[dst], m) @ Wb_upd[i] + bb_upd[i])
        gemm_k<3, 384, 3><<<NEDGE / 64, 256>>>(nullptr, Wb_upd + (size_t)i * 49152,
                                               bb_upd + i * 128, nullptr, pM, pM,
                                               emb, z, atype, src, dst);
    }

    // pred_cart_coord_diff
    force_k<<<NCRYST, 256>>>(W_force, b_force, dst, out);

    // atom-type head
    gemm_k<0, 128, 1><<<NATOMS / 64, 256>>>(pH, W_fc1, b_fc1, nullptr, nullptr,
                                            pA1, emb, z, atype, src, dst);
    gemm_k<0, 128, 1><<<NATOMS / 64, 256>>>(pA1, W_fc2, b_fc2, nullptr, nullptr,
                                            pA2, emb, z, atype, src, dst);
    fc3_k<<<NATOMS / 8, 256>>>(W_fc3, b_fc3, out + (size_t)NATOMS * 3);

    (void)in_sizes; (void)n_in; (void)out_size;
}

// round 3
// speedup vs baseline: 2.6574x; 2.6574x over previous
#include <cuda_runtime.h>
#include <cuda_bf16.h>
#include <cstdint>

// ---------------------------------------------------------------------------
// GemNetTDecoder — warp-level mma.sync bf16x3 (hi/lo split) version.
// tcgen05 is NOT available in this toolchain (PTX target sm_103 without 'a'),
// so big edge GEMMs use mma.sync.m16n8k16 bf16 with fp32 accum, 3 passes.
// ---------------------------------------------------------------------------

#define PI_F 3.14159265358979323846f

constexpr int NCRYST = 256;
constexpr int AA     = 64;
constexpr int KNB    = 20;
constexpr int HIDC   = 128;
constexpr int LATC   = 256;
constexpr int NATOMS = NCRYST * AA;       // 16384
constexpr int NEDGE  = NATOMS * KNB;      // 327680
constexpr float FCUT = 6.0f;
constexpr float DELTA = FCUT / 127.0f;

constexpr size_t EH = (size_t)NEDGE * HIDC;

// Weight buffer offsets (transposed [N=128, K] bf16 hi/lo)
constexpr int WOFF_EDGE = 0;                    // K=384 -> 49152
constexpr int WOFF_RBF  = 49152;                // 3 * 16384
constexpr int WOFF_MSG  = 98304;                // 3 * 16384
constexpr int WOFF_UPD  = 147456;               // 3 * 49152
constexpr int WTOT      = 294912;

// --------------------------- device scratch -------------------------------
__device__ float g_lat[NCRYST * 9];
__device__ float g_cart[NATOMS * 3];
__device__ float g_dist[NEDGE];
__device__ float g_env[NEDGE];
__device__ float g_unit[NEDGE * 3];
__device__ __nv_bfloat16 g_rbf_hi[EH];
__device__ __nv_bfloat16 g_rbf_lo[EH];
__device__ float g_h[NATOMS * HIDC];
__device__ float g_m[EH];
__device__ float g_msg[EH];
__device__ float g_agg[NATOMS * HIDC];
__device__ float g_a1[NATOMS * HIDC];
__device__ float g_a2[NATOMS * HIDC];
__device__ __nv_bfloat16 g_wt_hi[WTOT];
__device__ __nv_bfloat16 g_wt_lo[WTOT];

// --------------------------- helpers ---------------------------------------
__device__ __forceinline__ uint32_t smem_u32(const void* p) {
    uint32_t a;
    asm("{ .reg .u64 t; cvta.to.shared.u64 t, %1; cvt.u32.u64 %0, t; }"
        : "=r"(a) : "l"(p));
    return a;
}
__device__ __forceinline__ void ldm4(uint32_t* r, uint32_t a) {
    asm volatile("ldmatrix.sync.aligned.m8n8.x4.shared.b16 {%0,%1,%2,%3}, [%4];"
                 : "=r"(r[0]), "=r"(r[1]), "=r"(r[2]), "=r"(r[3]) : "r"(a));
}
__device__ __forceinline__ void mma16816(float* c, const uint32_t* a,
                                         const uint32_t* b) {
    asm volatile(
        "mma.sync.aligned.m16n8k16.row.col.f32.bf16.bf16.f32 "
        "{%0,%1,%2,%3}, {%4,%5,%6,%7}, {%8,%9}, {%0,%1,%2,%3};"
        : "+f"(c[0]), "+f"(c[1]), "+f"(c[2]), "+f"(c[3])
        : "r"(a[0]), "r"(a[1]), "r"(a[2]), "r"(a[3]), "r"(b[0]), "r"(b[1]));
}
__device__ __forceinline__ uint32_t pack_bf(__nv_bfloat16 a, __nv_bfloat16 b) {
    return (uint32_t)__bfloat16_as_ushort(a) |
           ((uint32_t)__bfloat16_as_ushort(b) << 16);
}
__device__ __forceinline__ void split4(float4 v, uint2& ph, uint2& pl) {
    __nv_bfloat16 h0 = __float2bfloat16(v.x), h1 = __float2bfloat16(v.y);
    __nv_bfloat16 h2 = __float2bfloat16(v.z), h3 = __float2bfloat16(v.w);
    ph.x = pack_bf(h0, h1);
    ph.y = pack_bf(h2, h3);
    pl.x = pack_bf(__float2bfloat16(v.x - __bfloat162float(h0)),
                   __float2bfloat16(v.y - __bfloat162float(h1)));
    pl.y = pack_bf(__float2bfloat16(v.z - __bfloat162float(h2)),
                   __float2bfloat16(v.w - __bfloat162float(h3)));
}

// smem layout (bytes): 4 tiles of 128 x 72 bf16 + bias + src + dst
constexpr int STR   = 72;                 // bf16 elements per smem row
constexpr int TILEB = 128 * STR * 2;      // 18432
constexpr int SA_HI = 0;
constexpr int SA_LO = TILEB;
constexpr int SB_HI = 2 * TILEB;
constexpr int SB_LO = 3 * TILEB;
constexpr int SBIAS = 4 * TILEB;          // 73728
constexpr int SSRC  = SBIAS + 512;
constexpr int SDST  = SSRC + 512;
constexpr int SMBYTES = SDST + 512;       // 75264

// --------------------------- small kernels --------------------------------
__global__ void lattice_k(const float* __restrict__ lengths,
                          const float* __restrict__ angles) {
    int i = threadIdx.x;
    if (i >= NCRYST) return;
    float r0 = angles[i * 3 + 0] * (PI_F / 180.f);
    float r1 = angles[i * 3 + 1] * (PI_F / 180.f);
    float r2 = angles[i * 3 + 2] * (PI_F / 180.f);
    float c0 = cosf(r0), c1 = cosf(r1), c2 = cosf(r2), sg = sinf(r2);
    float a = lengths[i * 3 + 0], b = lengths[i * 3 + 1], c = lengths[i * 3 + 2];
    float cx = c * c1;
    float cy = c * (c0 - c1 * c2) / sg;
    float cz = sqrtf(fmaxf(c * c - cx * cx - cy * cy, 1e-8f));
    float* L = &g_lat[i * 9];
    L[0] = a;      L[1] = 0.f;    L[2] = 0.f;
    L[3] = b * c2; L[4] = b * sg; L[5] = 0.f;
    L[6] = cx;     L[7] = cy;     L[8] = cz;
}

__global__ void cart_k(const float* __restrict__ frac) {
    int i = blockIdx.x * blockDim.x + threadIdx.x;
    if (i >= NATOMS) return;
    const float* L = &g_lat[(i >> 6) * 9];
    float f0 = frac[i * 3 + 0], f1 = frac[i * 3 + 1], f2 = frac[i * 3 + 2];
    g_cart[i * 3 + 0] = f0 * L[0] + f1 * L[3] + f2 * L[6];
    g_cart[i * 3 + 1] = f0 * L[1] + f1 * L[4] + f2 * L[7];
    g_cart[i * 3 + 2] = f0 * L[2] + f1 * L[5] + f2 * L[8];
}

__global__ void edge_k(const int* __restrict__ src, const int* __restrict__ dst) {
    int e = blockIdx.x * blockDim.x + threadIdx.x;
    if (e >= NEDGE) return;
    int s = src[e], d = dst[e];
    float dx = g_cart[d * 3 + 0] - g_cart[s * 3 + 0];
    float dy = g_cart[d * 3 + 1] - g_cart[s * 3 + 1];
    float dz = g_cart[d * 3 + 2] - g_cart[s * 3 + 2];
    float dist = sqrtf(dx * dx + dy * dy + dz * dz + 1e-12f);
    g_dist[e] = dist;
    float inv = 1.f / dist;
    g_unit[e * 3 + 0] = dx * inv;
    g_unit[e * 3 + 1] = dy * inv;
    g_unit[e * 3 + 2] = dz * inv;
    g_env[e] = 0.5f * (cosf(PI_F * fminf(dist * (1.f / FCUT), 1.f)) + 1.f);
}

__global__ void rbf_k() {
    int e = blockIdx.x * 2 + (threadIdx.x >> 7);
    int k = threadIdx.x & 127;
    float t = g_dist[e] * (1.f / DELTA) - (float)k;
    float v = __expf(-t * t) * g_env[e];
    __nv_bfloat16 hi = __float2bfloat16(v);
    size_t idx = (size_t)e * 128 + k;
    g_rbf_hi[idx] = hi;
    g_rbf_lo[idx] = __float2bfloat16(v - __bfloat162float(hi));
}

// transpose + hi/lo split:  W[K,128] -> hi/lo[128,K]
__global__ void wprep_k(const float* __restrict__ W, __nv_bfloat16* __restrict__ hi,
                        __nv_bfloat16* __restrict__ lo, int K) {
    int idx = blockIdx.x * 256 + threadIdx.x;
    if (idx >= K * 128) return;
    int k = idx >> 7, n = idx & 127;
    float v = W[idx];
    __nv_bfloat16 h = __float2bfloat16(v);
    hi[n * K + k] = h;
    lo[n * K + k] = __float2bfloat16(v - __bfloat162float(h));
}

// --------------------------- fp32 SIMT gemm (small) ------------------------
// MODE: 0 plain X[rows,KDIM] ; 1 concat(emb[atype], z[batch]) (KDIM=384)
// EPI : 1 relu(acc+bias) ; 3 base + relu(acc+bias)
template <int MODE, int KDIM, int EPI>
__global__ __launch_bounds__(256) void gemm_k(
    const float* __restrict__ X, const float* __restrict__ W,
    const float* __restrict__ bias, const float* __restrict__ base,
    float* __restrict__ out, const float* __restrict__ emb,
    const float* __restrict__ z, const int* __restrict__ atype) {
    __shared__ float Xs[16][68];
    __shared__ float Ws[16][128];
    __shared__ int sat[64];

    int row0 = blockIdx.x * 64;
    int tid = threadIdx.x;
    if (MODE == 1) {
        if (tid < 64) sat[tid] = atype[row0 + tid];
        __syncthreads();
    }

    int c0 = (tid & 15) * 8;
    int r0 = (tid >> 4) * 4;
    float acc[4][8];
#pragma unroll
    for (int i = 0; i < 4; i++)
#pragma unroll
        for (int j = 0; j < 8; j++) acc[i][j] = 0.f;

    for (int k0 = 0; k0 < KDIM; k0 += 16) {
#pragma unroll
        for (int t = 0; t < 4; t++) {
            int lin = tid * 4 + t;
            int r = lin >> 4, kk = lin & 15;
            int k = k0 + kk;
            float v;
            if (MODE == 0) {
                v = X[(size_t)(row0 + r) * KDIM + k];
            } else {
                v = (k < 128) ? emb[sat[r] * 128 + k]
                              : z[(size_t)((row0 + r) >> 6) * LATC + (k - 128)];
            }
            Xs[kk][r] = v;
        }
#pragma unroll
        for (int t = 0; t < 2; t++) {
            int i4 = tid + t * 256;
            int kk = i4 >> 5, n = (i4 & 31) * 4;
            *(float4*)&Ws[kk][n] = *(const float4*)&W[(size_t)(k0 + kk) * 128 + n];
        }
        __syncthreads();
#pragma unroll
        for (int kk = 0; kk < 16; kk++) {
            float4 a  = *(const float4*)&Xs[kk][r0];
            float4 b0 = *(const float4*)&Ws[kk][c0];
            float4 b1 = *(const float4*)&Ws[kk][c0 + 4];
            float av[4] = {a.x, a.y, a.z, a.w};
            float bv[8] = {b0.x, b0.y, b0.z, b0.w, b1.x, b1.y, b1.z, b1.w};
#pragma unroll
            for (int i = 0; i < 4; i++)
#pragma unroll
                for (int j = 0; j < 8; j++) acc[i][j] += av[i] * bv[j];
        }
        __syncthreads();
    }

    float bv[8];
    {
        float4 q0 = *(const float4*)&bias[c0];
        float4 q1 = *(const float4*)&bias[c0 + 4];
        bv[0] = q0.x; bv[1] = q0.y; bv[2] = q0.z; bv[3] = q0.w;
        bv[4] = q1.x; bv[5] = q1.y; bv[6] = q1.z; bv[7] = q1.w;
    }
#pragma unroll
    for (int i = 0; i < 4; i++) {
        size_t off = (size_t)(row0 + r0 + i) * 128 + c0;
        float v[8];
#pragma unroll
        for (int j = 0; j < 8; j++) v[j] = fmaxf(acc[i][j] + bv[j], 0.f);
        if (EPI == 3) {
            float4 bb0 = *(const float4*)&base[off];
            float4 bb1 = *(const float4*)&base[off + 4];
            v[0] += bb0.x; v[1] += bb0.y; v[2] += bb0.z; v[3] += bb0.w;
            v[4] += bb1.x; v[5] += bb1.y; v[6] += bb1.z; v[7] += bb1.w;
        }
        float4 o0 = {v[0], v[1], v[2], v[3]};
        float4 o1 = {v[4], v[5], v[6], v[7]};
        *(float4*)&out[off] = o0;
        *(float4*)&out[off + 4] = o1;
    }
}

// --------------------------- mma.sync edge GEMM ----------------------------
// out[row,128] = EPI( concat(h[src], h[dst], TAIL)[row, 0:384] @ W )
// MODE 2: TAIL = rbf (bf16 pre-split), EPI relu+bias, out = m
// MODE 3: TAIL = m   (fp32, convert),  EPI m += relu(acc+bias)
template <int MODE>
__global__ __launch_bounds__(256) void mma_edge_gemm(
    const __nv_bfloat16* __restrict__ wt_hi, const __nv_bfloat16* __restrict__ wt_lo,
    const float* __restrict__ bias, const int* __restrict__ srcp,
    const int* __restrict__ dstp, float* __restrict__ outm) {
    extern __shared__ char sm[];
    uint32_t sbase = smem_u32(sm);
    float* sbias = (float*)(sm + SBIAS);
    int* ssrc = (int*)(sm + SSRC);
    int* sdst = (int*)(sm + SDST);

    int tid = threadIdx.x;
    int row0 = blockIdx.x * 128;
    if (tid < 128) {
        ssrc[tid] = srcp[row0 + tid];
        sdst[tid] = dstp[row0 + tid];
        sbias[tid] = bias[tid];
    }

    int lane = tid & 31;
    int wm = (tid >> 5) & 3;   // M block (32 rows)
    int wn = tid >> 7;         // N block (64 cols)
    uint32_t a_row_l = (lane & 7) + ((lane >> 3) & 1) * 8;
    uint32_t a_k_l   = (lane >> 4) * 8;
    uint32_t b_n_l   = (lane & 7) + ((lane >> 4) & 1) * 8;
    uint32_t b_k_l   = ((lane >> 3) & 1) * 8;

    float acc[2][8][4];
#pragma unroll
    for (int i = 0; i < 2; i++)
#pragma unroll
        for (int j = 0; j < 8; j++)
#pragma unroll
            for (int q = 0; q < 4; q++) acc[i][j][q] = 0.f;

    for (int c = 0; c < 6; c++) {
        int kc = c * 64;
        __syncthreads();
        // ---- stage A chunk: 128 rows x 64 cols (hi/lo bf16)
#pragma unroll
        for (int t = 0; t < 8; t++) {
            int lin = t * 256 + tid;
            int r = lin >> 4;
            int col = (lin & 15) * 4;
            uint32_t so = ((uint32_t)r * STR + col) * 2;
            if (MODE == 2 && c >= 4) {
                size_t g = (size_t)(row0 + r) * 128 + (kc - 256) + col;
                *(uint2*)(sm + SA_HI + so) = *(const uint2*)(g_rbf_hi + g);
                *(uint2*)(sm + SA_LO + so) = *(const uint2*)(g_rbf_lo + g);
            } else {
                const float* sp;
                if (c < 2)      sp = g_h + (size_t)ssrc[r] * 128 + kc + col;
                else if (c < 4) sp = g_h + (size_t)sdst[r] * 128 + (kc - 128) + col;
                else            sp = g_m + (size_t)(row0 + r) * 128 + (kc - 256) + col;
                uint2 ph, pl;
                split4(*(const float4*)sp, ph, pl);
                *(uint2*)(sm + SA_HI + so) = ph;
                *(uint2*)(sm + SA_LO + so) = pl;
            }
        }
        // ---- stage B chunk: 128 N-rows x 64 K-cols (pre-split bf16)
#pragma unroll
        for (int t = 0; t < 8; t++) {
            int lin = t * 256 + tid;
            int n = lin >> 4;
            int col = (lin & 15) * 4;
            uint32_t so = ((uint32_t)n * STR + col) * 2;
            size_t g = (size_t)n * 384 + kc + col;
            *(uint2*)(sm + SB_HI + so) = *(const uint2*)(wt_hi + g);
            *(uint2*)(sm + SB_LO + so) = *(const uint2*)(wt_lo + g);
        }
        __syncthreads();
        // ---- mma over 4 k16 steps
#pragma unroll
        for (int k16 = 0; k16 < 4; k16++) {
            uint32_t kk = k16 * 16;
            uint32_t ah[2][4], al[2][4];
#pragma unroll
            for (int mi = 0; mi < 2; mi++) {
                uint32_t off = (((uint32_t)(wm * 32 + mi * 16) + a_row_l) * STR +
                                kk + a_k_l) * 2;
                ldm4(ah[mi], sbase + SA_HI + off);
                ldm4(al[mi], sbase + SA_LO + off);
            }
            uint32_t bh[8][2], bl[8][2];
#pragma unroll
            for (int p = 0; p < 4; p++) {
                uint32_t off = (((uint32_t)(wn * 64 + p * 16) + b_n_l) * STR +
                                kk + b_k_l) * 2;
                uint32_t r4[4];
                ldm4(r4, sbase + SB_HI + off);
                bh[2 * p][0] = r4[0]; bh[2 * p][1] = r4[1];
                bh[2 * p + 1][0] = r4[2]; bh[2 * p + 1][1] = r4[3];
                ldm4(r4, sbase + SB_LO + off);
                bl[2 * p][0] = r4[0]; bl[2 * p][1] = r4[1];
                bl[2 * p + 1][0] = r4[2]; bl[2 * p + 1][1] = r4[3];
            }
#pragma unroll
            for (int mi = 0; mi < 2; mi++)
#pragma unroll
                for (int nj = 0; nj < 8; nj++) {
                    mma16816(acc[mi][nj], ah[mi], bh[nj]);
                    mma16816(acc[mi][nj], ah[mi], bl[nj]);
                    mma16816(acc[mi][nj], al[mi], bh[nj]);
                }
        }
    }

    // ---- epilogue
    int r_base = row0 + wm * 32 + (lane >> 2);
    int c_base = wn * 64 + (lane & 3) * 2;
#pragma unroll
    for (int mi = 0; mi < 2; mi++)
#pragma unroll
        for (int nj = 0; nj < 8; nj++) {
            int row = r_base + mi * 16;
            int col = c_base + nj * 8;
            float2 bb = *(const float2*)&sbias[col];
#pragma unroll
            for (int half = 0; half < 2; half++) {
                size_t off = (size_t)(row + half * 8) * 128 + col;
                float v0 = fmaxf(acc[mi][nj][half * 2 + 0] + bb.x, 0.f);
                float v1 = fmaxf(acc[mi][nj][half * 2 + 1] + bb.y, 0.f);
                if (MODE == 3) {
                    float2 pr = *(const float2*)&outm[off];
                    v0 += pr.x; v1 += pr.y;
                }
                float2 o = {v0, v1};
                *(float2*)&outm[off] = o;
            }
        }
}

// --------------------------- mma.sync fused gate*msg -----------------------
// gate = rbf @ Wrbf ; msg = relu(m @ Wmsg + bias) * gate  -> g_msg
__global__ __launch_bounds__(256) void mma_gatemsg(
    const __nv_bfloat16* __restrict__ wrbf_hi, const __nv_bfloat16* __restrict__ wrbf_lo,
    const __nv_bfloat16* __restrict__ wmsg_hi, const __nv_bfloat16* __restrict__ wmsg_lo,
    const float* __restrict__ bias) {
    extern __shared__ char sm[];
    uint32_t sbase = smem_u32(sm);
    float* sbias = (float*)(sm + SBIAS);

    int tid = threadIdx.x;
    int row0 = blockIdx.x * 128;
    if (tid < 128) sbias[tid] = bias[tid];

    int lane = tid & 31;
    int wm = (tid >> 5) & 3;
    int wn = tid >> 7;
    uint32_t a_row_l = (lane & 7) + ((lane >> 3) & 1) * 8;
    uint32_t a_k_l   = (lane >> 4) * 8;
    uint32_t b_n_l   = (lane & 7) + ((lane >> 4) & 1) * 8;
    uint32_t b_k_l   = ((lane >> 3) & 1) * 8;

    float accg[2][8][4], accm[2][8][4];
#pragma unroll
    for (int i = 0; i < 2; i++)
#pragma unroll
        for (int j = 0; j < 8; j++)
#pragma unroll
            for (int q = 0; q < 4; q++) { accg[i][j][q] = 0.f; accm[i][j][q] = 0.f; }

    for (int c = 0; c < 4; c++) {
        bool is_gate = (c < 2);
        int kc = (c & 1) * 64;
        __syncthreads();
#pragma unroll
        for (int t = 0; t < 8; t++) {
            int lin = t * 256 + tid;
            int r = lin >> 4;
            int col = (lin & 15) * 4;
            uint32_t so = ((uint32_t)r * STR + col) * 2;
            size_t g = (size_t)(row0 + r) * 128 + kc + col;
            if (is_gate) {
                *(uint2*)(sm + SA_HI + so) = *(const uint2*)(g_rbf_hi + g);
                *(uint2*)(sm + SA_LO + so) = *(const uint2*)(g_rbf_lo + g);
            } else {
                uint2 ph, pl;
                split4(*(const float4*)(g_m + g), ph, pl);
                *(uint2*)(sm + SA_HI + so) = ph;
                *(uint2*)(sm + SA_LO + so) = pl;
            }
        }
        const __nv_bfloat16* whi = is_gate ? wrbf_hi : wmsg_hi;
        const __nv_bfloat16* wlo = is_gate ? wrbf_lo : wmsg_lo;
#pragma unroll
        for (int t = 0; t < 8; t++) {
            int lin = t * 256 + tid;
            int n = lin >> 4;
            int col = (lin & 15) * 4;
            uint32_t so = ((uint32_t)n * STR + col) * 2;
            size_t g = (size_t)n * 128 + kc + col;
            *(uint2*)(sm + SB_HI + so) = *(const uint2*)(whi + g);
            *(uint2*)(sm + SB_LO + so) = *(const uint2*)(wlo + g);
        }
        __syncthreads();
#pragma unroll
        for (int k16 = 0; k16 < 4; k16++) {
            uint32_t kk = k16 * 16;
            uint32_t ah[2][4], al[2][4];
#pragma unroll
            for (int mi = 0; mi < 2; mi++) {
                uint32_t off = (((uint32_t)(wm * 32 + mi * 16) + a_row_l) * STR +
                                kk + a_k_l) * 2;
                ldm4(ah[mi], sbase + SA_HI + off);
                ldm4(al[mi], sbase + SA_LO + off);
            }
            uint32_t bh[8][2], bl[8][2];
#pragma unroll
            for (int p = 0; p < 4; p++) {
                uint32_t off = (((uint32_t)(wn * 64 + p * 16) + b_n_l) * STR +
                                kk + b_k_l) * 2;
                uint32_t r4[4];
                ldm4(r4, sbase + SB_HI + off);
                bh[2 * p][0] = r4[0]; bh[2 * p][1] = r4[1];
                bh[2 * p + 1][0] = r4[2]; bh[2 * p + 1][1] = r4[3];
                ldm4(r4, sbase + SB_LO + off);
                bl[2 * p][0] = r4[0]; bl[2 * p][1] = r4[1];
                bl[2 * p + 1][0] = r4[2]; bl[2 * p + 1][1] = r4[3];
            }
#pragma unroll
            for (int mi = 0; mi < 2; mi++)
#pragma unroll
                for (int nj = 0; nj < 8; nj++) {
                    float* a = is_gate ? accg[mi][nj] : accm[mi][nj];
                    mma16816(a, ah[mi], bh[nj]);
                    mma16816(a, ah[mi], bl[nj]);
                    mma16816(a, al[mi], bh[nj]);
                }
        }
    }

    int r_base = row0 + wm * 32 + (lane >> 2);
    int c_base = wn * 64 + (lane & 3) * 2;
#pragma unroll
    for (int mi = 0; mi < 2; mi++)
#pragma unroll
        for (int nj = 0; nj < 8; nj++) {
            int row = r_base + mi * 16;
            int col = c_base + nj * 8;
            float2 bb = *(const float2*)&sbias[col];
#pragma unroll
            for (int half = 0; half < 2; half++) {
                size_t off = (size_t)(row + half * 8) * 128 + col;
                float v0 = fmaxf(accm[mi][nj][half * 2 + 0] + bb.x, 0.f) *
                           accg[mi][nj][half * 2 + 0];
                float v1 = fmaxf(accm[mi][nj][half * 2 + 1] + bb.y, 0.f) *
                           accg[mi][nj][half * 2 + 1];
                float2 o = {v0, v1};
                *(float2*)&g_msg[off] = o;
            }
        }
}

// --------------------------- segsum / force / fc3 --------------------------
__global__ __launch_bounds__(512) void segsum_k(const int* __restrict__ dst) {
    __shared__ float sagg[AA * HIDC];
    int c = blockIdx.x, tid = threadIdx.x;
    for (int i = tid; i < AA * HIDC; i += 512) sagg[i] = 0.f;
    __syncthreads();
    int col = tid & 127, grp = tid >> 7;
    int ebase = c * AA * KNB;
    for (int b = grp; b < AA * KNB; b += 4) {
        int e = ebase + b;
        int ld = dst[e] - (c << 6);
        atomicAdd(&sagg[ld * 128 + col], g_msg[(size_t)e * 128 + col]);
    }
    __syncthreads();
    for (int i = tid; i < AA * HIDC; i += 512)
        g_agg[(size_t)c * AA * HIDC + i] = sagg[i];
}

__global__ __launch_bounds__(256) void force_k(const float* __restrict__ Wf,
                                               const float* __restrict__ bf,
                                               const int* __restrict__ dst,
                                               float* __restrict__ out) {
    __shared__ float sW[128];
    __shared__ float sacc[AA * 3];
    int c = blockIdx.x, tid = threadIdx.x;
    if (tid < 128) sW[tid] = Wf[tid];
    if (tid < AA * 3) sacc[tid] = 0.f;
    __syncthreads();
    int w = tid >> 5, lane = tid & 31;
    float b0 = bf[0];
    for (int el = w; el < AA * KNB; el += 8) {
        int e = c * AA * KNB + el;
        const float* mr = &g_m[(size_t)e * 128];
        float p = 0.f;
#pragma unroll
        for (int k = lane; k < 128; k += 32) p += mr[k] * sW[k];
#pragma unroll
        for (int o = 16; o; o >>= 1) p += __shfl_xor_sync(0xffffffffu, p, o);
        float f = p + b0;
        int ld = dst[e] - (c << 6);
        if (lane < 3) atomicAdd(&sacc[ld * 3 + lane], f * g_unit[e * 3 + lane]);
    }
    __syncthreads();
    if (tid < AA * 3) out[(size_t)c * AA * 3 + tid] = sacc[tid];
}

__global__ __launch_bounds__(256) void fc3_k(const float* __restrict__ W,
                                             const float* __restrict__ b,
                                             float* __restrict__ out) {
    int atom = blockIdx.x * 8 + (threadIdx.x >> 5);
    int lane = threadIdx.x & 31;
    const float* ar = &g_a2[(size_t)atom * 128];
    float p0 = 0.f, p1 = 0.f;
#pragma unroll
    for (int k = lane; k < 128; k += 32) {
        float v = ar[k];
        p0 += v * W[k * 2 + 0];
        p1 += v * W[k * 2 + 1];
    }
#pragma unroll
    for (int o = 16; o; o >>= 1) {
        p0 += __shfl_xor_sync(0xffffffffu, p0, o);
        p1 += __shfl_xor_sync(0xffffffffu, p1, o);
    }
    if (lane == 0) {
        out[atom * 2 + 0] = p0 + b[0];
        out[atom * 2 + 1] = p1 + b[1];
    }
}

// ---------------------------------------------------------------------------
extern "C" void kernel_launch(void* const* d_in, const int* in_sizes, int n_in,
                              void* d_out, int out_size) {
    const float* z        = (const float*)d_in[0];
    const float* frac     = (const float*)d_in[1];
    const float* lengths  = (const float*)d_in[2];
    const float* angles   = (const float*)d_in[3];
    const int*   atype    = (const int*)d_in[4];
    const int*   src      = (const int*)d_in[5];
    const int*   dst      = (const int*)d_in[6];
    const float* emb      = (const float*)d_in[7];
    const float* W_in     = (const float*)d_in[8];
    const float* b_in     = (const float*)d_in[9];
    const float* W_edge   = (const float*)d_in[10];
    const float* b_edge   = (const float*)d_in[11];
    const float* Wb_rbf   = (const float*)d_in[12];
    const float* Wb_msg   = (const float*)d_in[13];
    const float* bb_msg   = (const float*)d_in[14];
    const float* Wb_atom  = (const float*)d_in[15];
    const float* bb_atom  = (const float*)d_in[16];
    const float* Wb_upd   = (const float*)d_in[17];
    const float* bb_upd   = (const float*)d_in[18];
    const float* W_force  = (const float*)d_in[19];
    const float* b_force  = (const float*)d_in[20];
    const float* W_fc1    = (const float*)d_in[21];
    const float* b_fc1    = (const float*)d_in[22];
    const float* W_fc2    = (const float*)d_in[23];
    const float* b_fc2    = (const float*)d_in[24];
    const float* W_fc3    = (const float*)d_in[25];
    const float* b_fc3    = (const float*)d_in[26];
    float* out = (float*)d_out;

    float *pH, *pM, *pAgg, *pA1, *pA2;
    __nv_bfloat16 *pWhi, *pWlo;
    cudaGetSymbolAddress((void**)&pH,   g_h);
    cudaGetSymbolAddress((void**)&pM,   g_m);
    cudaGetSymbolAddress((void**)&pAgg, g_agg);
    cudaGetSymbolAddress((void**)&pA1,  g_a1);
    cudaGetSymbolAddress((void**)&pA2,  g_a2);
    cudaGetSymbolAddress((void**)&pWhi, g_wt_hi);
    cudaGetSymbolAddress((void**)&pWlo, g_wt_lo);

    cudaFuncSetAttribute(mma_edge_gemm<2>,
                         cudaFuncAttributeMaxDynamicSharedMemorySize, SMBYTES);
    cudaFuncSetAttribute(mma_edge_gemm<3>,
                         cudaFuncAttributeMaxDynamicSharedMemorySize, SMBYTES);
    cudaFuncSetAttribute(mma_gatemsg,
                         cudaFuncAttributeMaxDynamicSharedMemorySize, SMBYTES);

    // geometry + rbf
    lattice_k<<<1, 256>>>(lengths, angles);
    cart_k<<<NATOMS / 256, 256>>>(frac);
    edge_k<<<NEDGE / 256, 256>>>(src, dst);
    rbf_k<<<NEDGE / 2, 256>>>();

    // weight prep (transpose + bf16 hi/lo split)
    wprep_k<<<192, 256>>>(W_edge, pWhi + WOFF_EDGE, pWlo + WOFF_EDGE, 384);
    for (int i = 0; i < 3; i++) {
        wprep_k<<<64, 256>>>(Wb_rbf + (size_t)i * 16384,
                             pWhi + WOFF_RBF + i * 16384, pWlo + WOFF_RBF + i * 16384, 128);
        wprep_k<<<64, 256>>>(Wb_msg + (size_t)i * 16384,
                             pWhi + WOFF_MSG + i * 16384, pWlo + WOFF_MSG + i * 16384, 128);
        wprep_k<<<192, 256>>>(Wb_upd + (size_t)i * 49152,
                              pWhi + WOFF_UPD + i * 49152, pWlo + WOFF_UPD + i * 49152, 384);
    }

    // h = relu(concat(emb, z) @ W_in + b_in)   (fp32 SIMT)
    gemm_k<1, 384, 1><<<NATOMS / 64, 256>>>(nullptr, W_in, b_in, nullptr, pH,
                                            emb, z, atype);
    // m = relu(concat(h[src], h[dst], rbf) @ W_edge + b_edge)   (mma)
    mma_edge_gemm<2><<<NEDGE / 128, 256, SMBYTES>>>(
        pWhi + WOFF_EDGE, pWlo + WOFF_EDGE, b_edge, src, dst, pM);

    for (int i = 0; i < 3; i++) {
        // msg = relu(m@Wmsg + b) * (rbf@Wrbf)   (mma, fused)
        mma_gatemsg<<<NEDGE / 128, 256, SMBYTES>>>(
            pWhi + WOFF_RBF + i * 16384, pWlo + WOFF_RBF + i * 16384,
            pWhi + WOFF_MSG + i * 16384, pWlo + WOFF_MSG + i * 16384,
            bb_msg + i * 128);
        segsum_k<<<NCRYST, 512>>>(dst);
        // h += relu(agg @ Wb_atom + b)   (fp32)
        gemm_k<0, 128, 3><<<NATOMS / 64, 256>>>(pAgg, Wb_atom + (size_t)i * 16384,
                                                bb_atom + i * 128, pH, pH,
                                                emb, z, atype);
        // m += relu(concat(h[src],h[dst],m) @ Wb_upd + b)   (mma)
        mma_edge_gemm<3><<<NEDGE / 128, 256, SMBYTES>>>(
            pWhi + WOFF_UPD + i * 49152, pWlo + WOFF_UPD + i * 49152,
            bb_upd + i * 128, src, dst, pM);
    }

    force_k<<<NCRYST, 256>>>(W_force, b_force, dst, out);

    gemm_k<0, 128, 1><<<NATOMS / 64, 256>>>(pH, W_fc1, b_fc1, nullptr, pA1,
                                            emb, z, atype);
    gemm_k<0, 128, 1><<<NATOMS / 64, 256>>>(pA1, W_fc2, b_fc2, nullptr, pA2,
                                            emb, z, atype);
    fc3_k<<<NATOMS / 8, 256>>>(W_fc3, b_fc3, out + (size_t)NATOMS * 3);

    (void)in_sizes; (void)n_in; (void)out_size;
}

// round 4
// speedup vs baseline: 2.7061x; 1.0183x over previous
#include <cuda_runtime.h>
#include <cuda_bf16.h>
#include <cstdint>

// ---------------------------------------------------------------------------
// GemNetTDecoder — mma.sync bf16x3 with pre-split hi/lo storage + cp.async
// double-buffered staging. All hot-loop A/B staging is copy-only.
// ---------------------------------------------------------------------------

#define PI_F 3.14159265358979323846f

constexpr int NCRYST = 256;
constexpr int AA     = 64;
constexpr int KNB    = 20;
constexpr int HIDC   = 128;
constexpr int LATC   = 256;
constexpr int NATOMS = NCRYST * AA;       // 16384
constexpr int NEDGE  = NATOMS * KNB;      // 327680
constexpr float FCUT = 6.0f;
constexpr float DELTA = FCUT / 127.0f;

constexpr size_t EH = (size_t)NEDGE * HIDC;

// Weight buffer offsets (transposed [N=128, K] bf16 hi/lo)
constexpr int WOFF_EDGE = 0;                    // K=384 -> 49152
constexpr int WOFF_RBF  = 49152;                // 3 * 16384
constexpr int WOFF_MSG  = 98304;                // 3 * 16384
constexpr int WOFF_UPD  = 147456;               // 3 * 49152
constexpr int WTOT      = 294912;

// --------------------------- device scratch -------------------------------
__device__ float g_lat[NCRYST * 9];
__device__ float g_cart[NATOMS * 3];
__device__ float g_dist[NEDGE];
__device__ float g_env[NEDGE];
__device__ float g_unit[NEDGE * 3];
__device__ __nv_bfloat16 g_rbf_hi[EH];
__device__ __nv_bfloat16 g_rbf_lo[EH];
__device__ float g_h[NATOMS * HIDC];
__device__ __nv_bfloat16 g_h_hi[NATOMS * HIDC];
__device__ __nv_bfloat16 g_h_lo[NATOMS * HIDC];
__device__ __nv_bfloat16 g_m_hi[EH];
__device__ __nv_bfloat16 g_m_lo[EH];
__device__ float g_msg[EH];
__device__ float g_agg[NATOMS * HIDC];
__device__ float g_a1[NATOMS * HIDC];
__device__ float g_a2[NATOMS * HIDC];
__device__ __nv_bfloat16 g_wt_hi[WTOT];
__device__ __nv_bfloat16 g_wt_lo[WTOT];

// --------------------------- helpers ---------------------------------------
__device__ __forceinline__ uint32_t smem_u32(const void* p) {
    uint32_t a;
    asm("{ .reg .u64 t; cvta.to.shared.u64 t, %1; cvt.u32.u64 %0, t; }"
        : "=r"(a) : "l"(p));
    return a;
}
__device__ __forceinline__ void ldm4(uint32_t* r, uint32_t a) {
    asm volatile("ldmatrix.sync.aligned.m8n8.x4.shared.b16 {%0,%1,%2,%3}, [%4];"
                 : "=r"(r[0]), "=r"(r[1]), "=r"(r[2]), "=r"(r[3]) : "r"(a));
}
__device__ __forceinline__ void mma16816(float* c, const uint32_t* a,
                                         const uint32_t* b) {
    asm volatile(
        "mma.sync.aligned.m16n8k16.row.col.f32.bf16.bf16.f32 "
        "{%0,%1,%2,%3}, {%4,%5,%6,%7}, {%8,%9}, {%0,%1,%2,%3};"
        : "+f"(c[0]), "+f"(c[1]), "+f"(c[2]), "+f"(c[3])
        : "r"(a[0]), "r"(a[1]), "r"(a[2]), "r"(a[3]), "r"(b[0]), "r"(b[1]));
}
__device__ __forceinline__ void cp16(uint32_t dst, const void* src) {
    asm volatile("cp.async.cg.shared.global [%0], [%1], 16;"
                 :: "r"(dst), "l"(src) : "memory");
}
__device__ __forceinline__ void cp_commit() {
    asm volatile("cp.async.commit_group;" ::: "memory");
}
__device__ __forceinline__ void cp_wait0() {
    asm volatile("cp.async.wait_group 0;" ::: "memory");
}
__device__ __forceinline__ void cp_wait1() {
    asm volatile("cp.async.wait_group 1;" ::: "memory");
}
__device__ __forceinline__ uint32_t pack_bf(__nv_bfloat16 a, __nv_bfloat16 b) {
    return (uint32_t)__bfloat16_as_ushort(a) |
           ((uint32_t)__bfloat16_as_ushort(b) << 16);
}
// split a float pair into packed hi-uint and lo-uint
__device__ __forceinline__ void split2(float v0, float v1, uint32_t& hi,
                                       uint32_t& lo) {
    __nv_bfloat16 h0 = __float2bfloat16(v0), h1 = __float2bfloat16(v1);
    hi = pack_bf(h0, h1);
    lo = pack_bf(__float2bfloat16(v0 - __bfloat162float(h0)),
                 __float2bfloat16(v1 - __bfloat162float(h1)));
}

// smem: 2 stages x (A_hi, A_lo, B_hi, B_lo tiles of 128 x 72 bf16)
constexpr int STR   = 72;                 // bf16 per smem row (144 B, 16B mult)
constexpr int TILEB = 128 * STR * 2;      // 18432
constexpr int SA_HI = 0;
constexpr int SA_LO = TILEB;
constexpr int SB_HI = 2 * TILEB;
constexpr int SB_LO = 3 * TILEB;
constexpr int STAGE = 4 * TILEB;          // 73728
constexpr int SBIAS = 2 * STAGE;          // 147456
constexpr int SSRC  = SBIAS + 512;
constexpr int SDST  = SSRC + 512;
constexpr int SMBYTES = SDST + 512;       // 148992

// --------------------------- small kernels --------------------------------
__global__ void lattice_k(const float* __restrict__ lengths,
                          const float* __restrict__ angles) {
    int i = threadIdx.x;
    if (i >= NCRYST) return;
    float r0 = angles[i * 3 + 0] * (PI_F / 180.f);
    float r1 = angles[i * 3 + 1] * (PI_F / 180.f);
    float r2 = angles[i * 3 + 2] * (PI_F / 180.f);
    float c0 = cosf(r0), c1 = cosf(r1), c2 = cosf(r2), sg = sinf(r2);
    float a = lengths[i * 3 + 0], b = lengths[i * 3 + 1], c = lengths[i * 3 + 2];
    float cx = c * c1;
    float cy = c * (c0 - c1 * c2) / sg;
    float cz = sqrtf(fmaxf(c * c - cx * cx - cy * cy, 1e-8f));
    float* L = &g_lat[i * 9];
    L[0] = a;      L[1] = 0.f;    L[2] = 0.f;
    L[3] = b * c2; L[4] = b * sg; L[5] = 0.f;
    L[6] = cx;     L[7] = cy;     L[8] = cz;
}

__global__ void cart_k(const float* __restrict__ frac) {
    int i = blockIdx.x * blockDim.x + threadIdx.x;
    if (i >= NATOMS) return;
    const float* L = &g_lat[(i >> 6) * 9];
    float f0 = frac[i * 3 + 0], f1 = frac[i * 3 + 1], f2 = frac[i * 3 + 2];
    g_cart[i * 3 + 0] = f0 * L[0] + f1 * L[3] + f2 * L[6];
    g_cart[i * 3 + 1] = f0 * L[1] + f1 * L[4] + f2 * L[7];
    g_cart[i * 3 + 2] = f0 * L[2] + f1 * L[5] + f2 * L[8];
}

__global__ void edge_k(const int* __restrict__ src, const int* __restrict__ dst) {
    int e = blockIdx.x * blockDim.x + threadIdx.x;
    if (e >= NEDGE) return;
    int s = src[e], d = dst[e];
    float dx = g_cart[d * 3 + 0] - g_cart[s * 3 + 0];
    float dy = g_cart[d * 3 + 1] - g_cart[s * 3 + 1];
    float dz = g_cart[d * 3 + 2] - g_cart[s * 3 + 2];
    float dist = sqrtf(dx * dx + dy * dy + dz * dz + 1e-12f);
    g_dist[e] = dist;
    float inv = 1.f / dist;
    g_unit[e * 3 + 0] = dx * inv;
    g_unit[e * 3 + 1] = dy * inv;
    g_unit[e * 3 + 2] = dz * inv;
    g_env[e] = 0.5f * (cosf(PI_F * fminf(dist * (1.f / FCUT), 1.f)) + 1.f);
}

// 4 rbf values per thread, vectorized hi/lo stores
__global__ __launch_bounds__(256) void rbf_k() {
    int gid = blockIdx.x * 256 + threadIdx.x;
    int e = gid >> 5;
    int k0 = (gid & 31) * 4;
    float ds = g_dist[e] * (1.f / DELTA);
    float env = g_env[e];
    uint32_t hi[2], lo[2];
#pragma unroll
    for (int p = 0; p < 2; p++) {
        float t0 = ds - (float)(k0 + 2 * p);
        float t1 = ds - (float)(k0 + 2 * p + 1);
        float v0 = __expf(-t0 * t0) * env;
        float v1 = __expf(-t1 * t1) * env;
        split2(v0, v1, hi[p], lo[p]);
    }
    size_t idx = (size_t)e * 128 + k0;
    *(uint2*)&g_rbf_hi[idx] = make_uint2(hi[0], hi[1]);
    *(uint2*)&g_rbf_lo[idx] = make_uint2(lo[0], lo[1]);
}

// transpose + hi/lo split:  W[K,128] -> hi/lo[128,K]
__global__ void wprep_k(const float* __restrict__ W, __nv_bfloat16* __restrict__ hi,
                        __nv_bfloat16* __restrict__ lo, int K) {
    int idx = blockIdx.x * 256 + threadIdx.x;
    if (idx >= K * 128) return;
    int k = idx >> 7, n = idx & 127;
    float v = W[idx];
    __nv_bfloat16 h = __float2bfloat16(v);
    hi[n * K + k] = h;
    lo[n * K + k] = __float2bfloat16(v - __bfloat162float(h));
}

// --------------------------- fp32 SIMT gemm (small) ------------------------
// MODE: 0 plain X[rows,KDIM] ; 1 concat(emb[atype], z[batch]) (KDIM=384)
// EPI : 1 relu(acc+bias) ; 3 base + relu(acc+bias)
// SPLIT: also write bf16 hi/lo planes of the output
template <int MODE, int KDIM, int EPI, int SPLIT>
__global__ __launch_bounds__(256) void gemm_k(
    const float* __restrict__ X, const float* __restrict__ W,
    const float* __restrict__ bias, const float* __restrict__ base,
    float* __restrict__ out, __nv_bfloat16* __restrict__ outhi,
    __nv_bfloat16* __restrict__ outlo, const float* __restrict__ emb,
    const float* __restrict__ z, const int* __restrict__ atype) {
    __shared__ float Xs[16][68];
    __shared__ float Ws[16][128];
    __shared__ int sat[64];

    int row0 = blockIdx.x * 64;
    int tid = threadIdx.x;
    if (MODE == 1) {
        if (tid < 64) sat[tid] = atype[row0 + tid];
        __syncthreads();
    }

    int c0 = (tid & 15) * 8;
    int r0 = (tid >> 4) * 4;
    float acc[4][8];
#pragma unroll
    for (int i = 0; i < 4; i++)
#pragma unroll
        for (int j = 0; j < 8; j++) acc[i][j] = 0.f;

    for (int k0 = 0; k0 < KDIM; k0 += 16) {
#pragma unroll
        for (int t = 0; t < 4; t++) {
            int lin = tid * 4 + t;
            int r = lin >> 4, kk = lin & 15;
            int k = k0 + kk;
            float v;
            if (MODE == 0) {
                v = X[(size_t)(row0 + r) * KDIM + k];
            } else {
                v = (k < 128) ? emb[sat[r] * 128 + k]
                              : z[(size_t)((row0 + r) >> 6) * LATC + (k - 128)];
            }
            Xs[kk][r] = v;
        }
#pragma unroll
        for (int t = 0; t < 2; t++) {
            int i4 = tid + t * 256;
            int kk = i4 >> 5, n = (i4 & 31) * 4;
            *(float4*)&Ws[kk][n] = *(const float4*)&W[(size_t)(k0 + kk) * 128 + n];
        }
        __syncthreads();
#pragma unroll
        for (int kk = 0; kk < 16; kk++) {
            float4 a  = *(const float4*)&Xs[kk][r0];
            float4 b0 = *(const float4*)&Ws[kk][c0];
            float4 b1 = *(const float4*)&Ws[kk][c0 + 4];
            float av[4] = {a.x, a.y, a.z, a.w};
            float bv[8] = {b0.x, b0.y, b0.z, b0.w, b1.x, b1.y, b1.z, b1.w};
#pragma unroll
            for (int i = 0; i < 4; i++)
#pragma unroll
                for (int j = 0; j < 8; j++) acc[i][j] += av[i] * bv[j];
        }
        __syncthreads();
    }

    float bv[8];
    {
        float4 q0 = *(const float4*)&bias[c0];
        float4 q1 = *(const float4*)&bias[c0 + 4];
        bv[0] = q0.x; bv[1] = q0.y; bv[2] = q0.z; bv[3] = q0.w;
        bv[4] = q1.x; bv[5] = q1.y; bv[6] = q1.z; bv[7] = q1.w;
    }
#pragma unroll
    for (int i = 0; i < 4; i++) {
        size_t off = (size_t)(row0 + r0 + i) * 128 + c0;
        float v[8];
#pragma unroll
        for (int j = 0; j < 8; j++) v[j] = fmaxf(acc[i][j] + bv[j], 0.f);
        if (EPI == 3) {
            float4 bb0 = *(const float4*)&base[off];
            float4 bb1 = *(const float4*)&base[off + 4];
            v[0] += bb0.x; v[1] += bb0.y; v[2] += bb0.z; v[3] += bb0.w;
            v[4] += bb1.x; v[5] += bb1.y; v[6] += bb1.z; v[7] += bb1.w;
        }
        float4 o0 = {v[0], v[1], v[2], v[3]};
        float4 o1 = {v[4], v[5], v[6], v[7]};
        *(float4*)&out[off] = o0;
        *(float4*)&out[off + 4] = o1;
        if (SPLIT) {
            uint32_t hh[4], ll[4];
#pragma unroll
            for (int q = 0; q < 4; q++) split2(v[2 * q], v[2 * q + 1], hh[q], ll[q]);
            *(uint4*)&outhi[off] = make_uint4(hh[0], hh[1], hh[2], hh[3]);
            *(uint4*)&outlo[off] = make_uint4(ll[0], ll[1], ll[2], ll[3]);
        }
    }
}

// --------------------------- mma.sync edge GEMM ----------------------------
// m_out[row,128] = EPI( concat(h[src], h[dst], TAIL)[row, 0:384] @ W )
// MODE 2: TAIL = rbf, EPI relu+bias, m = result
// MODE 3: TAIL = m,   EPI m += relu(acc+bias)
template <int MODE>
__global__ __launch_bounds__(256) void mma_edge_gemm(
    const __nv_bfloat16* __restrict__ wt_hi, const __nv_bfloat16* __restrict__ wt_lo,
    const float* __restrict__ bias, const int* __restrict__ srcp,
    const int* __restrict__ dstp) {
    extern __shared__ char sm[];
    uint32_t sbase = smem_u32(sm);
    float* sbias = (float*)(sm + SBIAS);
    int* ssrc = (int*)(sm + SSRC);
    int* sdst = (int*)(sm + SDST);

    int tid = threadIdx.x;
    int row0 = blockIdx.x * 128;
    if (tid < 128) {
        ssrc[tid] = srcp[row0 + tid];
        sdst[tid] = dstp[row0 + tid];
        sbias[tid] = bias[tid];
    }
    __syncthreads();

    auto prefetch = [&](int c, int s) {
        int kc = c * 64;
        uint32_t st = sbase + s * STAGE;
#pragma unroll
        for (int i = 0; i < 8; i++) {
            int lin = i * 256 + tid;
            int plane = lin >> 10;
            int idx = lin & 1023;
            int row = idx >> 3;
            int seg = idx & 7;
            const __nv_bfloat16* ap;
            if (c >= 4) {
                if (MODE == 2)
                    ap = (plane ? g_rbf_lo : g_rbf_hi) +
                         (size_t)(row0 + row) * 128 + (kc - 256) + seg * 8;
                else
                    ap = (plane ? g_m_lo : g_m_hi) +
                         (size_t)(row0 + row) * 128 + (kc - 256) + seg * 8;
            } else if (c < 2) {
                ap = (plane ? g_h_lo : g_h_hi) + (size_t)ssrc[row] * 128 + kc + seg * 8;
            } else {
                ap = (plane ? g_h_lo : g_h_hi) + (size_t)sdst[row] * 128 +
                     (kc - 128) + seg * 8;
            }
            cp16(st + (plane ? SA_LO : SA_HI) + row * 144 + seg * 16, ap);
            const __nv_bfloat16* bp =
                (plane ? wt_lo : wt_hi) + (size_t)row * 384 + kc + seg * 8;
            cp16(st + (plane ? SB_LO : SB_HI) + row * 144 + seg * 16, bp);
        }
        cp_commit();
    };

    int lane = tid & 31;
    int wm = (tid >> 5) & 3;   // M block (32 rows)
    int wn = tid >> 7;         // N block (64 cols)
    uint32_t a_row_l = (lane & 7) + ((lane >> 3) & 1) * 8;
    uint32_t a_k_l   = (lane >> 4) * 8;
    uint32_t b_n_l   = (lane & 7) + ((lane >> 4) & 1) * 8;
    uint32_t b_k_l   = ((lane >> 3) & 1) * 8;

    float acc[2][8][4];
#pragma unroll
    for (int i = 0; i < 2; i++)
#pragma unroll
        for (int j = 0; j < 8; j++)
#pragma unroll
            for (int q = 0; q < 4; q++) acc[i][j][q] = 0.f;

    prefetch(0, 0);
    prefetch(1, 1);

    for (int c = 0; c < 6; c++) {
        if (c + 1 < 6) cp_wait1(); else cp_wait0();
        __syncthreads();
        uint32_t st = sbase + (c & 1) * STAGE;
#pragma unroll
        for (int k16 = 0; k16 < 4; k16++) {
            uint32_t kk = k16 * 16;
            uint32_t ah[2][4], al[2][4];
#pragma unroll
            for (int mi = 0; mi < 2; mi++) {
                uint32_t off = (((uint32_t)(wm * 32 + mi * 16) + a_row_l) * STR +
                                kk + a_k_l) * 2;
                ldm4(ah[mi], st + SA_HI + off);
                ldm4(al[mi], st + SA_LO + off);
            }
            uint32_t bh[8][2], bl[8][2];
#pragma unroll
            for (int p = 0; p < 4; p++) {
                uint32_t off = (((uint32_t)(wn * 64 + p * 16) + b_n_l) * STR +
                                kk + b_k_l) * 2;
                uint32_t r4[4];
                ldm4(r4, st + SB_HI + off);
                bh[2 * p][0] = r4[0]; bh[2 * p][1] = r4[1];
                bh[2 * p + 1][0] = r4[2]; bh[2 * p + 1][1] = r4[3];
                ldm4(r4, st + SB_LO + off);
                bl[2 * p][0] = r4[0]; bl[2 * p][1] = r4[1];
                bl[2 * p + 1][0] = r4[2]; bl[2 * p + 1][1] = r4[3];
            }
#pragma unroll
            for (int mi = 0; mi < 2; mi++)
#pragma unroll
                for (int nj = 0; nj < 8; nj++) {
                    mma16816(acc[mi][nj], ah[mi], bh[nj]);
                    mma16816(acc[mi][nj], ah[mi], bl[nj]);
                    mma16816(acc[mi][nj], al[mi], bh[nj]);
                }
        }
        __syncthreads();
        if (c + 2 < 6) prefetch(c + 2, c & 1);
    }

    // ---- epilogue: write m as hi/lo planes
    int r_base = row0 + wm * 32 + (lane >> 2);
    int c_base = wn * 64 + (lane & 3) * 2;
#pragma unroll
    for (int mi = 0; mi < 2; mi++)
#pragma unroll
        for (int nj = 0; nj < 8; nj++) {
            int row = r_base + mi * 16;
            int col = c_base + nj * 8;
            float2 bb = *(const float2*)&sbias[col];
#pragma unroll
            for (int half = 0; half < 2; half++) {
                size_t off = (size_t)(row + half * 8) * 128 + col;
                float v0 = fmaxf(acc[mi][nj][half * 2 + 0] + bb.x, 0.f);
                float v1 = fmaxf(acc[mi][nj][half * 2 + 1] + bb.y, 0.f);
                if (MODE == 3) {
                    uint32_t oh = *(const uint32_t*)&g_m_hi[off];
                    uint32_t ol = *(const uint32_t*)&g_m_lo[off];
                    v0 += __bfloat162float(__ushort_as_bfloat16(oh & 0xffff)) +
                          __bfloat162float(__ushort_as_bfloat16(ol & 0xffff));
                    v1 += __bfloat162float(__ushort_as_bfloat16(oh >> 16)) +
                          __bfloat162float(__ushort_as_bfloat16(ol >> 16));
                }
                uint32_t hh, ll;
                split2(v0, v1, hh, ll);
                *(uint32_t*)&g_m_hi[off] = hh;
                *(uint32_t*)&g_m_lo[off] = ll;
            }
        }
}

// --------------------------- mma.sync fused gate*msg -----------------------
// gate = rbf @ Wrbf ; msg = relu(m @ Wmsg + bias) * gate  -> g_msg (fp32)
__global__ __launch_bounds__(256) void mma_gatemsg(
    const __nv_bfloat16* __restrict__ wrbf_hi, const __nv_bfloat16* __restrict__ wrbf_lo,
    const __nv_bfloat16* __restrict__ wmsg_hi, const __nv_bfloat16* __restrict__ wmsg_lo,
    const float* __restrict__ bias) {
    extern __shared__ char sm[];
    uint32_t sbase = smem_u32(sm);
    float* sbias = (float*)(sm + SBIAS);

    int tid = threadIdx.x;
    int row0 = blockIdx.x * 128;
    if (tid < 128) sbias[tid] = bias[tid];
    __syncthreads();

    auto prefetch = [&](int c, int s) {
        bool is_gate = (c < 2);
        int kc = (c & 1) * 64;
        uint32_t st = sbase + s * STAGE;
        const __nv_bfloat16* ahi = is_gate ? g_rbf_hi : g_m_hi;
        const __nv_bfloat16* alo = is_gate ? g_rbf_lo : g_m_lo;
        const __nv_bfloat16* whi = is_gate ? wrbf_hi : wmsg_hi;
        const __nv_bfloat16* wlo = is_gate ? wrbf_lo : wmsg_lo;
#pragma unroll
        for (int i = 0; i < 8; i++) {
            int lin = i * 256 + tid;
            int plane = lin >> 10;
            int idx = lin & 1023;
            int row = idx >> 3;
            int seg = idx & 7;
            const __nv_bfloat16* ap =
                (plane ? alo : ahi) + (size_t)(row0 + row) * 128 + kc + seg * 8;
            cp16(st + (plane ? SA_LO : SA_HI) + row * 144 + seg * 16, ap);
            const __nv_bfloat16* bp =
                (plane ? wlo : whi) + (size_t)row * 128 + kc + seg * 8;
            cp16(st + (plane ? SB_LO : SB_HI) + row * 144 + seg * 16, bp);
        }
        cp_commit();
    };

    int lane = tid & 31;
    int wm = (tid >> 5) & 3;
    int wn = tid >> 7;
    uint32_t a_row_l = (lane & 7) + ((lane >> 3) & 1) * 8;
    uint32_t a_k_l   = (lane >> 4) * 8;
    uint32_t b_n_l   = (lane & 7) + ((lane >> 4) & 1) * 8;
    uint32_t b_k_l   = ((lane >> 3) & 1) * 8;

    float accg[2][8][4], accm[2][8][4];
#pragma unroll
    for (int i = 0; i < 2; i++)
#pragma unroll
        for (int j = 0; j < 8; j++)
#pragma unroll
            for (int q = 0; q < 4; q++) { accg[i][j][q] = 0.f; accm[i][j][q] = 0.f; }

    prefetch(0, 0);
    prefetch(1, 1);

    for (int c = 0; c < 4; c++) {
        bool is_gate = (c < 2);
        if (c + 1 < 4) cp_wait1(); else cp_wait0();
        __syncthreads();
        uint32_t st = sbase + (c & 1) * STAGE;
#pragma unroll
        for (int k16 = 0; k16 < 4; k16++) {
            uint32_t kk = k16 * 16;
            uint32_t ah[2][4], al[2][4];
#pragma unroll
            for (int mi = 0; mi < 2; mi++) {
                uint32_t off = (((uint32_t)(wm * 32 + mi * 16) + a_row_l) * STR +
                                kk + a_k_l) * 2;
                ldm4(ah[mi], st + SA_HI + off);
                ldm4(al[mi], st + SA_LO + off);
            }
            uint32_t bh[8][2], bl[8][2];
#pragma unroll
            for (int p = 0; p < 4; p++) {
                uint32_t off = (((uint32_t)(wn * 64 + p * 16) + b_n_l) * STR +
                                kk + b_k_l) * 2;
                uint32_t r4[4];
                ldm4(r4, st + SB_HI + off);
                bh[2 * p][0] = r4[0]; bh[2 * p][1] = r4[1];
                bh[2 * p + 1][0] = r4[2]; bh[2 * p + 1][1] = r4[3];
                ldm4(r4, st + SB_LO + off);
                bl[2 * p][0] = r4[0]; bl[2 * p][1] = r4[1];
                bl[2 * p + 1][0] = r4[2]; bl[2 * p + 1][1] = r4[3];
            }
#pragma unroll
            for (int mi = 0; mi < 2; mi++)
#pragma unroll
                for (int nj = 0; nj < 8; nj++) {
                    float* a = is_gate ? accg[mi][nj] : accm[mi][nj];
                    mma16816(a, ah[mi], bh[nj]);
                    mma16816(a, ah[mi], bl[nj]);
                    mma16816(a, al[mi], bh[nj]);
                }
        }
        __syncthreads();
        if (c + 2 < 4) prefetch(c + 2, c & 1);
    }

    int r_base = row0 + wm * 32 + (lane >> 2);
    int c_base = wn * 64 + (lane & 3) * 2;
#pragma unroll
    for (int mi = 0; mi < 2; mi++)
#pragma unroll
        for (int nj = 0; nj < 8; nj++) {
            int row = r_base + mi * 16;
            int col = c_base + nj * 8;
            float2 bb = *(const float2*)&sbias[col];
#pragma unroll
            for (int half = 0; half < 2; half++) {
                size_t off = (size_t)(row + half * 8) * 128 + col;
                float v0 = fmaxf(accm[mi][nj][half * 2 + 0] + bb.x, 0.f) *
                           accg[mi][nj][half * 2 + 0];
                float v1 = fmaxf(accm[mi][nj][half * 2 + 1] + bb.y, 0.f) *
                           accg[mi][nj][half * 2 + 1];
                float2 o = {v0, v1};
                *(float2*)&g_msg[off] = o;
            }
        }
}

// --------------------------- segsum / force / fc3 --------------------------
__global__ __launch_bounds__(512) void segsum_k(const int* __restrict__ dst) {
    __shared__ float sagg[AA * HIDC];
    int c = blockIdx.x, tid = threadIdx.x;
    for (int i = tid; i < AA * HIDC; i += 512) sagg[i] = 0.f;
    __syncthreads();
    int col = tid & 127, grp = tid >> 7;
    int ebase = c * AA * KNB;
    for (int b = grp; b < AA * KNB; b += 4) {
        int e = ebase + b;
        int ld = dst[e] - (c << 6);
        atomicAdd(&sagg[ld * 128 + col], g_msg[(size_t)e * 128 + col]);
    }
    __syncthreads();
    for (int i = tid; i < AA * HIDC; i += 512)
        g_agg[(size_t)c * AA * HIDC + i] = sagg[i];
}

__global__ __launch_bounds__(256) void force_k(const float* __restrict__ Wf,
                                               const float* __restrict__ bf,
                                               const int* __restrict__ dst,
                                               float* __restrict__ out) {
    __shared__ float sW[128];
    __shared__ float sacc[AA * 3];
    int c = blockIdx.x, tid = threadIdx.x;
    if (tid < 128) sW[tid] = Wf[tid];
    if (tid < AA * 3) sacc[tid] = 0.f;
    __syncthreads();
    int w = tid >> 5, lane = tid & 31;
    float b0 = bf[0];
    for (int el = w; el < AA * KNB; el += 8) {
        int e = c * AA * KNB + el;
        size_t base = (size_t)e * 128;
        float p = 0.f;
#pragma unroll
        for (int k = lane; k < 128; k += 32) {
            float v = __bfloat162float(g_m_hi[base + k]) +
                      __bfloat162float(g_m_lo[base + k]);
            p += v * sW[k];
        }
#pragma unroll
        for (int o = 16; o; o >>= 1) p += __shfl_xor_sync(0xffffffffu, p, o);
        float f = p + b0;
        int ld = dst[e] - (c << 6);
        if (lane < 3) atomicAdd(&sacc[ld * 3 + lane], f * g_unit[e * 3 + lane]);
    }
    __syncthreads();
    if (tid < AA * 3) out[(size_t)c * AA * 3 + tid] = sacc[tid];
}

__global__ __launch_bounds__(256) void fc3_k(const float* __restrict__ W,
                                             const float* __restrict__ b,
                                             float* __restrict__ out) {
    int atom = blockIdx.x * 8 + (threadIdx.x >> 5);
    int lane = threadIdx.x & 31;
    const float* ar = &g_a2[(size_t)atom * 128];
    float p0 = 0.f, p1 = 0.f;
#pragma unroll
    for (int k = lane; k < 128; k += 32) {
        float v = ar[k];
        p0 += v * W[k * 2 + 0];
        p1 += v * W[k * 2 + 1];
    }
#pragma unroll
    for (int o = 16; o; o >>= 1) {
        p0 += __shfl_xor_sync(0xffffffffu, p0, o);
        p1 += __shfl_xor_sync(0xffffffffu, p1, o);
    }
    if (lane == 0) {
        out[atom * 2 + 0] = p0 + b[0];
        out[atom * 2 + 1] = p1 + b[1];
    }
}

// ---------------------------------------------------------------------------
extern "C" void kernel_launch(void* const* d_in, const int* in_sizes, int n_in,
                              void* d_out, int out_size) {
    const float* z        = (const float*)d_in[0];
    const float* frac     = (const float*)d_in[1];
    const float* lengths  = (const float*)d_in[2];
    const float* angles   = (const float*)d_in[3];
    const int*   atype    = (const int*)d_in[4];
    const int*   src      = (const int*)d_in[5];
    const int*   dst      = (const int*)d_in[6];
    const float* emb      = (const float*)d_in[7];
    const float* W_in     = (const float*)d_in[8];
    const float* b_in     = (const float*)d_in[9];
    const float* W_edge   = (const float*)d_in[10];
    const float* b_edge   = (const float*)d_in[11];
    const float* Wb_rbf   = (const float*)d_in[12];
    const float* Wb_msg   = (const float*)d_in[13];
    const float* bb_msg   = (const float*)d_in[14];
    const float* Wb_atom  = (const float*)d_in[15];
    const float* bb_atom  = (const float*)d_in[16];
    const float* Wb_upd   = (const float*)d_in[17];
    const float* bb_upd   = (const float*)d_in[18];
    const float* W_force  = (const float*)d_in[19];
    const float* b_force  = (const float*)d_in[20];
    const float* W_fc1    = (const float*)d_in[21];
    const float* b_fc1    = (const float*)d_in[22];
    const float* W_fc2    = (const float*)d_in[23];
    const float* b_fc2    = (const float*)d_in[24];
    const float* W_fc3    = (const float*)d_in[25];
    const float* b_fc3    = (const float*)d_in[26];
    float* out = (float*)d_out;

    float *pH, *pAgg, *pA1, *pA2;
    __nv_bfloat16 *pWhi, *pWlo, *pHhi, *pHlo;
    cudaGetSymbolAddress((void**)&pH,   g_h);
    cudaGetSymbolAddress((void**)&pAgg, g_agg);
    cudaGetSymbolAddress((void**)&pA1,  g_a1);
    cudaGetSymbolAddress((void**)&pA2,  g_a2);
    cudaGetSymbolAddress((void**)&pWhi, g_wt_hi);
    cudaGetSymbolAddress((void**)&pWlo, g_wt_lo);
    cudaGetSymbolAddress((void**)&pHhi, g_h_hi);
    cudaGetSymbolAddress((void**)&pHlo, g_h_lo);

    cudaFuncSetAttribute(mma_edge_gemm<2>,
                         cudaFuncAttributeMaxDynamicSharedMemorySize, SMBYTES);
    cudaFuncSetAttribute(mma_edge_gemm<3>,
                         cudaFuncAttributeMaxDynamicSharedMemorySize, SMBYTES);
    cudaFuncSetAttribute(mma_gatemsg,
                         cudaFuncAttributeMaxDynamicSharedMemorySize, SMBYTES);

    // geometry + rbf
    lattice_k<<<1, 256>>>(lengths, angles);
    cart_k<<<NATOMS / 256, 256>>>(frac);
    edge_k<<<NEDGE / 256, 256>>>(src, dst);
    rbf_k<<<NEDGE / 8, 256>>>();

    // weight prep (transpose + bf16 hi/lo split)
    wprep_k<<<192, 256>>>(W_edge, pWhi + WOFF_EDGE, pWlo + WOFF_EDGE, 384);
    for (int i = 0; i < 3; i++) {
        wprep_k<<<64, 256>>>(Wb_rbf + (size_t)i * 16384,
                             pWhi + WOFF_RBF + i * 16384, pWlo + WOFF_RBF + i * 16384, 128);
        wprep_k<<<64, 256>>>(Wb_msg + (size_t)i * 16384,
                             pWhi + WOFF_MSG + i * 16384, pWlo + WOFF_MSG + i * 16384, 128);
        wprep_k<<<192, 256>>>(Wb_upd + (size_t)i * 49152,
                              pWhi + WOFF_UPD + i * 49152, pWlo + WOFF_UPD + i * 49152, 384);
    }

    // h = relu(concat(emb, z) @ W_in + b_in)   (fp32 SIMT, split output)
    gemm_k<1, 384, 1, 1><<<NATOMS / 64, 256>>>(nullptr, W_in, b_in, nullptr, pH,
                                               pHhi, pHlo, emb, z, atype);
    // m = relu(concat(h[src], h[dst], rbf) @ W_edge + b_edge)   (mma)
    mma_edge_gemm<2><<<NEDGE / 128, 256, SMBYTES>>>(
        pWhi + WOFF_EDGE, pWlo + WOFF_EDGE, b_edge, src, dst);

    for (int i = 0; i < 3; i++) {
        // msg = relu(m@Wmsg + b) * (rbf@Wrbf)   (mma, fused)
        mma_gatemsg<<<NEDGE / 128, 256, SMBYTES>>>(
            pWhi + WOFF_RBF + i * 16384, pWlo + WOFF_RBF + i * 16384,
            pWhi + WOFF_MSG + i * 16384, pWlo + WOFF_MSG + i * 16384,
            bb_msg + i * 128);
        segsum_k<<<NCRYST, 512>>>(dst);
        // h += relu(agg @ Wb_atom + b)   (fp32, split output)
        gemm_k<0, 128, 3, 1><<<NATOMS / 64, 256>>>(pAgg, Wb_atom + (size_t)i * 16384,
                                                   bb_atom + i * 128, pH, pH,
                                                   pHhi, pHlo, emb, z, atype);
        // m += relu(concat(h[src],h[dst],m) @ Wb_upd + b)   (mma)
        mma_edge_gemm<3><<<NEDGE / 128, 256, SMBYTES>>>(
            pWhi + WOFF_UPD + i * 49152, pWlo + WOFF_UPD + i * 49152,
            bb_upd + i * 128, src, dst);
    }

    force_k<<<NCRYST, 256>>>(W_force, b_force, dst, out);

    gemm_k<0, 128, 1, 0><<<NATOMS / 64, 256>>>(pH, W_fc1, b_fc1, nullptr, pA1,
                                               nullptr, nullptr, emb, z, atype);
    gemm_k<0, 128, 1, 0><<<NATOMS / 64, 256>>>(pA1, W_fc2, b_fc2, nullptr, pA2,
                                               nullptr, nullptr, emb, z, atype);
    fc3_k<<<NATOMS / 8, 256>>>(W_fc3, b_fc3, out + (size_t)NATOMS * 3);

    (void)in_sizes; (void)n_in; (void)out_size;
}

// round 5
// speedup vs baseline: 3.1774x; 1.1741x over previous
#include <cuda_runtime.h>
#include <cuda_bf16.h>
#include <cstdint>

// ---------------------------------------------------------------------------
// GemNetTDecoder — mma.sync bf16x3, pre-split hi/lo storage, cp.async staging.
// R5: edge GEMMs single-stage @ 2 CTAs/SM; gate*msg GEMM fuses segment-sum
// into its epilogue (msg never touches DRAM).
// ---------------------------------------------------------------------------

#define PI_F 3.14159265358979323846f

constexpr int NCRYST = 256;
constexpr int AA     = 64;
constexpr int KNB    = 20;
constexpr int HIDC   = 128;
constexpr int LATC   = 256;
constexpr int NATOMS = NCRYST * AA;       // 16384
constexpr int NEDGE  = NATOMS * KNB;      // 327680
constexpr float FCUT = 6.0f;
constexpr float DELTA = FCUT / 127.0f;

constexpr size_t EH = (size_t)NEDGE * HIDC;

constexpr int WOFF_EDGE = 0;
constexpr int WOFF_RBF  = 49152;
constexpr int WOFF_MSG  = 98304;
constexpr int WOFF_UPD  = 147456;
constexpr int WTOT      = 294912;

// --------------------------- device scratch -------------------------------
__device__ float g_lat[NCRYST * 9];
__device__ float g_cart[NATOMS * 3];
__device__ float g_dist[NEDGE];
__device__ float g_env[NEDGE];
__device__ float g_unit[NEDGE * 3];
__device__ __nv_bfloat16 g_rbf_hi[EH];
__device__ __nv_bfloat16 g_rbf_lo[EH];
__device__ float g_h[NATOMS * HIDC];
__device__ __nv_bfloat16 g_h_hi[NATOMS * HIDC];
__device__ __nv_bfloat16 g_h_lo[NATOMS * HIDC];
__device__ __nv_bfloat16 g_m_hi[EH];
__device__ __nv_bfloat16 g_m_lo[EH];
__device__ float g_agg[NATOMS * HIDC];
__device__ float g_a1[NATOMS * HIDC];
__device__ float g_a2[NATOMS * HIDC];
__device__ __nv_bfloat16 g_wt_hi[WTOT];
__device__ __nv_bfloat16 g_wt_lo[WTOT];

// --------------------------- helpers ---------------------------------------
__device__ __forceinline__ uint32_t smem_u32(const void* p) {
    uint32_t a;
    asm("{ .reg .u64 t; cvta.to.shared.u64 t, %1; cvt.u32.u64 %0, t; }"
        : "=r"(a) : "l"(p));
    return a;
}
__device__ __forceinline__ void ldm4(uint32_t* r, uint32_t a) {
    asm volatile("ldmatrix.sync.aligned.m8n8.x4.shared.b16 {%0,%1,%2,%3}, [%4];"
                 : "=r"(r[0]), "=r"(r[1]), "=r"(r[2]), "=r"(r[3]) : "r"(a));
}
__device__ __forceinline__ void mma16816(float* c, const uint32_t* a,
                                         const uint32_t* b) {
    asm volatile(
        "mma.sync.aligned.m16n8k16.row.col.f32.bf16.bf16.f32 "
        "{%0,%1,%2,%3}, {%4,%5,%6,%7}, {%8,%9}, {%0,%1,%2,%3};"
        : "+f"(c[0]), "+f"(c[1]), "+f"(c[2]), "+f"(c[3])
        : "r"(a[0]), "r"(a[1]), "r"(a[2]), "r"(a[3]), "r"(b[0]), "r"(b[1]));
}
__device__ __forceinline__ void cp16(uint32_t dst, const void* src) {
    asm volatile("cp.async.cg.shared.global [%0], [%1], 16;"
                 :: "r"(dst), "l"(src) : "memory");
}
__device__ __forceinline__ void cp_commit() {
    asm volatile("cp.async.commit_group;" ::: "memory");
}
__device__ __forceinline__ void cp_wait0() {
    asm volatile("cp.async.wait_group 0;" ::: "memory");
}
__device__ __forceinline__ void cp_wait1() {
    asm volatile("cp.async.wait_group 1;" ::: "memory");
}
__device__ __forceinline__ uint32_t pack_bf(__nv_bfloat16 a, __nv_bfloat16 b) {
    return (uint32_t)__bfloat16_as_ushort(a) |
           ((uint32_t)__bfloat16_as_ushort(b) << 16);
}
__device__ __forceinline__ void split2(float v0, float v1, uint32_t& hi,
                                       uint32_t& lo) {
    __nv_bfloat16 h0 = __float2bfloat16(v0), h1 = __float2bfloat16(v1);
    hi = pack_bf(h0, h1);
    lo = pack_bf(__float2bfloat16(v0 - __bfloat162float(h0)),
                 __float2bfloat16(v1 - __bfloat162float(h1)));
}

// smem tile geometry
constexpr int STR   = 72;                 // bf16 per smem row (144 B)
constexpr int TILEB = 128 * STR * 2;      // 18432
constexpr int SA_HI = 0;
constexpr int SA_LO = TILEB;
constexpr int SB_HI = 2 * TILEB;
constexpr int SB_LO = 3 * TILEB;
constexpr int STAGE = 4 * TILEB;          // 73728

// edge gemm: single stage + misc  (2 CTAs/SM)
constexpr int E_BIAS = STAGE;
constexpr int E_SRC  = E_BIAS + 512;
constexpr int E_DST  = E_SRC + 512;
constexpr int SMB_EDGE = E_DST + 512;     // 75264

// gatemsg: two stages + misc  (1 CTA/SM); sagg aliases stage 0
constexpr int G_BIAS = 2 * STAGE;         // 147456
constexpr int G_DST  = G_BIAS + 512;
constexpr int SMB_GM = G_DST + 512;       // 148480

// --------------------------- small kernels --------------------------------
__global__ void lattice_k(const float* __restrict__ lengths,
                          const float* __restrict__ angles) {
    int i = threadIdx.x;
    if (i >= NCRYST) return;
    float r0 = angles[i * 3 + 0] * (PI_F / 180.f);
    float r1 = angles[i * 3 + 1] * (PI_F / 180.f);
    float r2 = angles[i * 3 + 2] * (PI_F / 180.f);
    float c0 = cosf(r0), c1 = cosf(r1), c2 = cosf(r2), sg = sinf(r2);
    float a = lengths[i * 3 + 0], b = lengths[i * 3 + 1], c = lengths[i * 3 + 2];
    float cx = c * c1;
    float cy = c * (c0 - c1 * c2) / sg;
    float cz = sqrtf(fmaxf(c * c - cx * cx - cy * cy, 1e-8f));
    float* L = &g_lat[i * 9];
    L[0] = a;      L[1] = 0.f;    L[2] = 0.f;
    L[3] = b * c2; L[4] = b * sg; L[5] = 0.f;
    L[6] = cx;     L[7] = cy;     L[8] = cz;
}

__global__ void cart_k(const float* __restrict__ frac) {
    int i = blockIdx.x * blockDim.x + threadIdx.x;
    if (i >= NATOMS) return;
    const float* L = &g_lat[(i >> 6) * 9];
    float f0 = frac[i * 3 + 0], f1 = frac[i * 3 + 1], f2 = frac[i * 3 + 2];
    g_cart[i * 3 + 0] = f0 * L[0] + f1 * L[3] + f2 * L[6];
    g_cart[i * 3 + 1] = f0 * L[1] + f1 * L[4] + f2 * L[7];
    g_cart[i * 3 + 2] = f0 * L[2] + f1 * L[5] + f2 * L[8];
}

__global__ void edge_k(const int* __restrict__ src, const int* __restrict__ dst) {
    int e = blockIdx.x * blockDim.x + threadIdx.x;
    if (e >= NEDGE) return;
    int s = src[e], d = dst[e];
    float dx = g_cart[d * 3 + 0] - g_cart[s * 3 + 0];
    float dy = g_cart[d * 3 + 1] - g_cart[s * 3 + 1];
    float dz = g_cart[d * 3 + 2] - g_cart[s * 3 + 2];
    float dist = sqrtf(dx * dx + dy * dy + dz * dz + 1e-12f);
    g_dist[e] = dist;
    float inv = 1.f / dist;
    g_unit[e * 3 + 0] = dx * inv;
    g_unit[e * 3 + 1] = dy * inv;
    g_unit[e * 3 + 2] = dz * inv;
    g_env[e] = 0.5f * (cosf(PI_F * fminf(dist * (1.f / FCUT), 1.f)) + 1.f);
}

__global__ __launch_bounds__(256) void rbf_k() {
    int gid = blockIdx.x * 256 + threadIdx.x;
    int e = gid >> 5;
    int k0 = (gid & 31) * 4;
    float ds = g_dist[e] * (1.f / DELTA);
    float env = g_env[e];
    uint32_t hi[2], lo[2];
#pragma unroll
    for (int p = 0; p < 2; p++) {
        float t0 = ds - (float)(k0 + 2 * p);
        float t1 = ds - (float)(k0 + 2 * p + 1);
        float v0 = __expf(-t0 * t0) * env;
        float v1 = __expf(-t1 * t1) * env;
        split2(v0, v1, hi[p], lo[p]);
    }
    size_t idx = (size_t)e * 128 + k0;
    *(uint2*)&g_rbf_hi[idx] = make_uint2(hi[0], hi[1]);
    *(uint2*)&g_rbf_lo[idx] = make_uint2(lo[0], lo[1]);
}

__global__ void wprep_k(const float* __restrict__ W, __nv_bfloat16* __restrict__ hi,
                        __nv_bfloat16* __restrict__ lo, int K) {
    int idx = blockIdx.x * 256 + threadIdx.x;
    if (idx >= K * 128) return;
    int k = idx >> 7, n = idx & 127;
    float v = W[idx];
    __nv_bfloat16 h = __float2bfloat16(v);
    hi[n * K + k] = h;
    lo[n * K + k] = __float2bfloat16(v - __bfloat162float(h));
}

__global__ void zero_agg_k() {
    int i = blockIdx.x * 256 + threadIdx.x;
    *(float4*)&g_agg[(size_t)i * 4] = make_float4(0.f, 0.f, 0.f, 0.f);
}

// --------------------------- fp32 SIMT gemm (small) ------------------------
template <int MODE, int KDIM, int EPI, int SPLIT>
__global__ __launch_bounds__(256) void gemm_k(
    const float* __restrict__ X, const float* __restrict__ W,
    const float* __restrict__ bias, const float* __restrict__ base,
    float* __restrict__ out, __nv_bfloat16* __restrict__ outhi,
    __nv_bfloat16* __restrict__ outlo, const float* __restrict__ emb,
    const float* __restrict__ z, const int* __restrict__ atype) {
    __shared__ float Xs[16][68];
    __shared__ float Ws[16][128];
    __shared__ int sat[64];

    int row0 = blockIdx.x * 64;
    int tid = threadIdx.x;
    if (MODE == 1) {
        if (tid < 64) sat[tid] = atype[row0 + tid];
        __syncthreads();
    }

    int c0 = (tid & 15) * 8;
    int r0 = (tid >> 4) * 4;
    float acc[4][8];
#pragma unroll
    for (int i = 0; i < 4; i++)
#pragma unroll
        for (int j = 0; j < 8; j++) acc[i][j] = 0.f;

    for (int k0 = 0; k0 < KDIM; k0 += 16) {
#pragma unroll
        for (int t = 0; t < 4; t++) {
            int lin = tid * 4 + t;
            int r = lin >> 4, kk = lin & 15;
            int k = k0 + kk;
            float v;
            if (MODE == 0) {
                v = X[(size_t)(row0 + r) * KDIM + k];
            } else {
                v = (k < 128) ? emb[sat[r] * 128 + k]
                              : z[(size_t)((row0 + r) >> 6) * LATC + (k - 128)];
            }
            Xs[kk][r] = v;
        }
#pragma unroll
        for (int t = 0; t < 2; t++) {
            int i4 = tid + t * 256;
            int kk = i4 >> 5, n = (i4 & 31) * 4;
            *(float4*)&Ws[kk][n] = *(const float4*)&W[(size_t)(k0 + kk) * 128 + n];
        }
        __syncthreads();
#pragma unroll
        for (int kk = 0; kk < 16; kk++) {
            float4 a  = *(const float4*)&Xs[kk][r0];
            float4 b0 = *(const float4*)&Ws[kk][c0];
            float4 b1 = *(const float4*)&Ws[kk][c0 + 4];
            float av[4] = {a.x, a.y, a.z, a.w};
            float bv[8] = {b0.x, b0.y, b0.z, b0.w, b1.x, b1.y, b1.z, b1.w};
#pragma unroll
            for (int i = 0; i < 4; i++)
#pragma unroll
                for (int j = 0; j < 8; j++) acc[i][j] += av[i] * bv[j];
        }
        __syncthreads();
    }

    float bv[8];
    {
        float4 q0 = *(const float4*)&bias[c0];
        float4 q1 = *(const float4*)&bias[c0 + 4];
        bv[0] = q0.x; bv[1] = q0.y; bv[2] = q0.z; bv[3] = q0.w;
        bv[4] = q1.x; bv[5] = q1.y; bv[6] = q1.z; bv[7] = q1.w;
    }
#pragma unroll
    for (int i = 0; i < 4; i++) {
        size_t off = (size_t)(row0 + r0 + i) * 128 + c0;
        float v[8];
#pragma unroll
        for (int j = 0; j < 8; j++) v[j] = fmaxf(acc[i][j] + bv[j], 0.f);
        if (EPI == 3) {
            float4 bb0 = *(const float4*)&base[off];
            float4 bb1 = *(const float4*)&base[off + 4];
            v[0] += bb0.x; v[1] += bb0.y; v[2] += bb0.z; v[3] += bb0.w;
            v[4] += bb1.x; v[5] += bb1.y; v[6] += bb1.z; v[7] += bb1.w;
        }
        float4 o0 = {v[0], v[1], v[2], v[3]};
        float4 o1 = {v[4], v[5], v[6], v[7]};
        *(float4*)&out[off] = o0;
        *(float4*)&out[off + 4] = o1;
        if (SPLIT) {
            uint32_t hh[4], ll[4];
#pragma unroll
            for (int q = 0; q < 4; q++) split2(v[2 * q], v[2 * q + 1], hh[q], ll[q]);
            *(uint4*)&outhi[off] = make_uint4(hh[0], hh[1], hh[2], hh[3]);
            *(uint4*)&outlo[off] = make_uint4(ll[0], ll[1], ll[2], ll[3]);
        }
    }
}

// --------------------------- mma.sync edge GEMM ----------------------------
// MODE 2: TAIL = rbf, m = relu(acc+bias)
// MODE 3: TAIL = m,   m += relu(acc+bias)
// Single-stage staging, 2 CTAs/SM.
template <int MODE>
__global__ __launch_bounds__(256, 2) void mma_edge_gemm(
    const __nv_bfloat16* __restrict__ wt_hi, const __nv_bfloat16* __restrict__ wt_lo,
    const float* __restrict__ bias, const int* __restrict__ srcp,
    const int* __restrict__ dstp) {
    extern __shared__ char sm[];
    uint32_t sbase = smem_u32(sm);
    float* sbias = (float*)(sm + E_BIAS);
    int* ssrc = (int*)(sm + E_SRC);
    int* sdst = (int*)(sm + E_DST);

    int tid = threadIdx.x;
    int row0 = blockIdx.x * 128;
    if (tid < 128) {
        ssrc[tid] = srcp[row0 + tid];
        sdst[tid] = dstp[row0 + tid];
        sbias[tid] = bias[tid];
    }
    __syncthreads();

    auto prefetch = [&](int c) {
        int kc = c * 64;
#pragma unroll
        for (int i = 0; i < 8; i++) {
            int lin = i * 256 + tid;
            int plane = lin >> 10;
            int idx = lin & 1023;
            int row = idx >> 3;
            int seg = idx & 7;
            const __nv_bfloat16* ap;
            if (c >= 4) {
                if (MODE == 2)
                    ap = (plane ? g_rbf_lo : g_rbf_hi) +
                         (size_t)(row0 + row) * 128 + (kc - 256) + seg * 8;
                else
                    ap = (plane ? g_m_lo : g_m_hi) +
                         (size_t)(row0 + row) * 128 + (kc - 256) + seg * 8;
            } else if (c < 2) {
                ap = (plane ? g_h_lo : g_h_hi) + (size_t)ssrc[row] * 128 + kc + seg * 8;
            } else {
                ap = (plane ? g_h_lo : g_h_hi) + (size_t)sdst[row] * 128 +
                     (kc - 128) + seg * 8;
            }
            cp16(sbase + (plane ? SA_LO : SA_HI) + row * 144 + seg * 16, ap);
            const __nv_bfloat16* bp =
                (plane ? wt_lo : wt_hi) + (size_t)row * 384 + kc + seg * 8;
            cp16(sbase + (plane ? SB_LO : SB_HI) + row * 144 + seg * 16, bp);
        }
        cp_commit();
    };

    int lane = tid & 31;
    int wm = (tid >> 5) & 3;
    int wn = tid >> 7;
    uint32_t a_row_l = (lane & 7) + ((lane >> 3) & 1) * 8;
    uint32_t a_k_l   = (lane >> 4) * 8;
    uint32_t b_n_l   = (lane & 7) + ((lane >> 4) & 1) * 8;
    uint32_t b_k_l   = ((lane >> 3) & 1) * 8;

    float acc[2][8][4];
#pragma unroll
    for (int i = 0; i < 2; i++)
#pragma unroll
        for (int j = 0; j < 8; j++)
#pragma unroll
            for (int q = 0; q < 4; q++) acc[i][j][q] = 0.f;

    for (int c = 0; c < 6; c++) {
        prefetch(c);
        cp_wait0();
        __syncthreads();
#pragma unroll
        for (int k16 = 0; k16 < 4; k16++) {
            uint32_t kk = k16 * 16;
            uint32_t ah[2][4], al[2][4];
#pragma unroll
            for (int mi = 0; mi < 2; mi++) {
                uint32_t off = (((uint32_t)(wm * 32 + mi * 16) + a_row_l) * STR +
                                kk + a_k_l) * 2;
                ldm4(ah[mi], sbase + SA_HI + off);
                ldm4(al[mi], sbase + SA_LO + off);
            }
#pragma unroll
            for (int p = 0; p < 4; p++) {
                uint32_t off = (((uint32_t)(wn * 64 + p * 16) + b_n_l) * STR +
                                kk + b_k_l) * 2;
                uint32_t r4[4], s4[4];
                ldm4(r4, sbase + SB_HI + off);
                ldm4(s4, sbase + SB_LO + off);
#pragma unroll
                for (int mi = 0; mi < 2; mi++) {
                    mma16816(acc[mi][2 * p],     ah[mi], &r4[0]);
                    mma16816(acc[mi][2 * p + 1], ah[mi], &r4[2]);
                    mma16816(acc[mi][2 * p],     ah[mi], &s4[0]);
                    mma16816(acc[mi][2 * p + 1], ah[mi], &s4[2]);
                    mma16816(acc[mi][2 * p],     al[mi], &r4[0]);
                    mma16816(acc[mi][2 * p + 1], al[mi], &r4[2]);
                }
            }
        }
        __syncthreads();
    }

    // epilogue: write m hi/lo planes (residual read hits L2 for MODE 3)
    int r_base = row0 + wm * 32 + (lane >> 2);
    int c_base = wn * 64 + (lane & 3) * 2;
#pragma unroll
    for (int mi = 0; mi < 2; mi++)
#pragma unroll
        for (int nj = 0; nj < 8; nj++) {
            int row = r_base + mi * 16;
            int col = c_base + nj * 8;
            float2 bb = *(const float2*)&sbias[col];
#pragma unroll
            for (int half = 0; half < 2; half++) {
                size_t off = (size_t)(row + half * 8) * 128 + col;
                float v0 = fmaxf(acc[mi][nj][half * 2 + 0] + bb.x, 0.f);
                float v1 = fmaxf(acc[mi][nj][half * 2 + 1] + bb.y, 0.f);
                if (MODE == 3) {
                    uint32_t oh = *(const uint32_t*)&g_m_hi[off];
                    uint32_t ol = *(const uint32_t*)&g_m_lo[off];
                    v0 += __bfloat162float(__ushort_as_bfloat16(oh & 0xffff)) +
                          __bfloat162float(__ushort_as_bfloat16(ol & 0xffff));
                    v1 += __bfloat162float(__ushort_as_bfloat16(oh >> 16)) +
                          __bfloat162float(__ushort_as_bfloat16(ol >> 16));
                }
                uint32_t hh, ll;
                split2(v0, v1, hh, ll);
                *(uint32_t*)&g_m_hi[off] = hh;
                *(uint32_t*)&g_m_lo[off] = ll;
            }
        }
}

// --------------------------- fused gate*msg + segment-sum ------------------
// gate = rbf @ Wrbf ; msg = relu(m @ Wmsg + bias) * gate ;
// agg[dst] += msg   (smem reduction + global atomics; msg never hits DRAM)
__global__ __launch_bounds__(256) void mma_gatemsg(
    const __nv_bfloat16* __restrict__ wrbf_hi, const __nv_bfloat16* __restrict__ wrbf_lo,
    const __nv_bfloat16* __restrict__ wmsg_hi, const __nv_bfloat16* __restrict__ wmsg_lo,
    const float* __restrict__ bias, const int* __restrict__ dstp) {
    extern __shared__ char sm[];
    uint32_t sbase = smem_u32(sm);
    float* sbias = (float*)(sm + G_BIAS);
    int* sdst = (int*)(sm + G_DST);

    int tid = threadIdx.x;
    int row0 = blockIdx.x * 128;
    if (tid < 128) {
        sbias[tid] = bias[tid];
        sdst[tid] = dstp[row0 + tid] & 63;   // atom local to its crystal
    }
    __syncthreads();

    auto prefetch = [&](int c, int s) {
        bool is_gate = (c < 2);
        int kc = (c & 1) * 64;
        uint32_t st = sbase + s * STAGE;
        const __nv_bfloat16* ahi = is_gate ? g_rbf_hi : g_m_hi;
        const __nv_bfloat16* alo = is_gate ? g_rbf_lo : g_m_lo;
        const __nv_bfloat16* whi = is_gate ? wrbf_hi : wmsg_hi;
        const __nv_bfloat16* wlo = is_gate ? wrbf_lo : wmsg_lo;
#pragma unroll
        for (int i = 0; i < 8; i++) {
            int lin = i * 256 + tid;
            int plane = lin >> 10;
            int idx = lin & 1023;
            int row = idx >> 3;
            int seg = idx & 7;
            const __nv_bfloat16* ap =
                (plane ? alo : ahi) + (size_t)(row0 + row) * 128 + kc + seg * 8;
            cp16(st + (plane ? SA_LO : SA_HI) + row * 144 + seg * 16, ap);
            const __nv_bfloat16* bp =
                (plane ? wlo : whi) + (size_t)row * 128 + kc + seg * 8;
            cp16(st + (plane ? SB_LO : SB_HI) + row * 144 + seg * 16, bp);
        }
        cp_commit();
    };

    int lane = tid & 31;
    int wm = (tid >> 5) & 3;
    int wn = tid >> 7;
    uint32_t a_row_l = (lane & 7) + ((lane >> 3) & 1) * 8;
    uint32_t a_k_l   = (lane >> 4) * 8;
    uint32_t b_n_l   = (lane & 7) + ((lane >> 4) & 1) * 8;
    uint32_t b_k_l   = ((lane >> 3) & 1) * 8;

    float accg[2][8][4], accm[2][8][4];
#pragma unroll
    for (int i = 0; i < 2; i++)
#pragma unroll
        for (int j = 0; j < 8; j++)
#pragma unroll
            for (int q = 0; q < 4; q++) { accg[i][j][q] = 0.f; accm[i][j][q] = 0.f; }

    prefetch(0, 0);
    prefetch(1, 1);

    for (int c = 0; c < 4; c++) {
        bool is_gate = (c < 2);
        if (c + 1 < 4) cp_wait1(); else cp_wait0();
        __syncthreads();
        uint32_t st = sbase + (c & 1) * STAGE;
#pragma unroll
        for (int k16 = 0; k16 < 4; k16++) {
            uint32_t kk = k16 * 16;
            uint32_t ah[2][4], al[2][4];
#pragma unroll
            for (int mi = 0; mi < 2; mi++) {
                uint32_t off = (((uint32_t)(wm * 32 + mi * 16) + a_row_l) * STR +
                                kk + a_k_l) * 2;
                ldm4(ah[mi], st + SA_HI + off);
                ldm4(al[mi], st + SA_LO + off);
            }
#pragma unroll
            for (int p = 0; p < 4; p++) {
                uint32_t off = (((uint32_t)(wn * 64 + p * 16) + b_n_l) * STR +
                                kk + b_k_l) * 2;
                uint32_t r4[4], s4[4];
                ldm4(r4, st + SB_HI + off);
                ldm4(s4, st + SB_LO + off);
#pragma unroll
                for (int mi = 0; mi < 2; mi++) {
                    float* a0 = is_gate ? accg[mi][2 * p] : accm[mi][2 * p];
                    float* a1 = is_gate ? accg[mi][2 * p + 1] : accm[mi][2 * p + 1];
                    mma16816(a0, ah[mi], &r4[0]);
                    mma16816(a1, ah[mi], &r4[2]);
                    mma16816(a0, ah[mi], &s4[0]);
                    mma16816(a1, ah[mi], &s4[2]);
                    mma16816(a0, al[mi], &r4[0]);
                    mma16816(a1, al[mi], &r4[2]);
                }
            }
        }
        __syncthreads();
        if (c + 2 < 4) prefetch(c + 2, c & 1);
    }

    // ---- fused epilogue: msg -> smem sagg (64 atoms x 128 cols) -> g_agg
    float* sagg = (float*)sm;   // alias stage buffers (done with MMA)
    for (int i = tid; i < AA * HIDC; i += 256) sagg[i] = 0.f;
    __syncthreads();

    int rl_base = wm * 32 + (lane >> 2);
    int c_base = wn * 64 + (lane & 3) * 2;
#pragma unroll
    for (int mi = 0; mi < 2; mi++)
#pragma unroll
        for (int half = 0; half < 2; half++) {
            int rl = rl_base + mi * 16 + half * 8;
            int ld = sdst[rl];
#pragma unroll
            for (int nj = 0; nj < 8; nj++) {
                int col = c_base + nj * 8;
                float v0 = fmaxf(accm[mi][nj][half * 2 + 0] + sbias[col], 0.f) *
                           accg[mi][nj][half * 2 + 0];
                float v1 = fmaxf(accm[mi][nj][half * 2 + 1] + sbias[col + 1], 0.f) *
                           accg[mi][nj][half * 2 + 1];
                atomicAdd(&sagg[ld * 128 + col], v0);
                atomicAdd(&sagg[ld * 128 + col + 1], v1);
            }
        }
    __syncthreads();

    size_t base = (size_t)(row0 / (AA * KNB)) * AA * HIDC;
    for (int i = tid; i < AA * HIDC; i += 256)
        atomicAdd(&g_agg[base + i], sagg[i]);
}

// --------------------------- force / fc3 -----------------------------------
__global__ __launch_bounds__(256) void force_k(const float* __restrict__ Wf,
                                               const float* __restrict__ bf,
                                               const int* __restrict__ dst,
                                               float* __restrict__ out) {
    __shared__ float sW[128];
    __shared__ float sacc[AA * 3];
    int c = blockIdx.x, tid = threadIdx.x;
    if (tid < 128) sW[tid] = Wf[tid];
    if (tid < AA * 3) sacc[tid] = 0.f;
    __syncthreads();
    int w = tid >> 5, lane = tid & 31;
    float b0 = bf[0];
    for (int el = w; el < AA * KNB; el += 8) {
        int e = c * AA * KNB + el;
        size_t base = (size_t)e * 128;
        float p = 0.f;
#pragma unroll
        for (int k = lane; k < 128; k += 32) {
            float v = __bfloat162float(g_m_hi[base + k]) +
                      __bfloat162float(g_m_lo[base + k]);
            p += v * sW[k];
        }
#pragma unroll
        for (int o = 16; o; o >>= 1) p += __shfl_xor_sync(0xffffffffu, p, o);
        float f = p + b0;
        int ld = dst[e] - (c << 6);
        if (lane < 3) atomicAdd(&sacc[ld * 3 + lane], f * g_unit[e * 3 + lane]);
    }
    __syncthreads();
    if (tid < AA * 3) out[(size_t)c * AA * 3 + tid] = sacc[tid];
}

__global__ __launch_bounds__(256) void fc3_k(const float* __restrict__ W,
                                             const float* __restrict__ b,
                                             float* __restrict__ out) {
    int atom = blockIdx.x * 8 + (threadIdx.x >> 5);
    int lane = threadIdx.x & 31;
    const float* ar = &g_a2[(size_t)atom * 128];
    float p0 = 0.f, p1 = 0.f;
#pragma unroll
    for (int k = lane; k < 128; k += 32) {
        float v = ar[k];
        p0 += v * W[k * 2 + 0];
        p1 += v * W[k * 2 + 1];
    }
#pragma unroll
    for (int o = 16; o; o >>= 1) {
        p0 += __shfl_xor_sync(0xffffffffu, p0, o);
        p1 += __shfl_xor_sync(0xffffffffu, p1, o);
    }
    if (lane == 0) {
        out[atom * 2 + 0] = p0 + b[0];
        out[atom * 2 + 1] = p1 + b[1];
    }
}

// ---------------------------------------------------------------------------
extern "C" void kernel_launch(void* const* d_in, const int* in_sizes, int n_in,
                              void* d_out, int out_size) {
    const float* z        = (const float*)d_in[0];
    const float* frac     = (const float*)d_in[1];
    const float* lengths  = (const float*)d_in[2];
    const float* angles   = (const float*)d_in[3];
    const int*   atype    = (const int*)d_in[4];
    const int*   src      = (const int*)d_in[5];
    const int*   dst      = (const int*)d_in[6];
    const float* emb      = (const float*)d_in[7];
    const float* W_in     = (const float*)d_in[8];
    const float* b_in     = (const float*)d_in[9];
    const float* W_edge   = (const float*)d_in[10];
    const float* b_edge   = (const float*)d_in[11];
    const float* Wb_rbf   = (const float*)d_in[12];
    const float* Wb_msg   = (const float*)d_in[13];
    const float* bb_msg   = (const float*)d_in[14];
    const float* Wb_atom  = (const float*)d_in[15];
    const float* bb_atom  = (const float*)d_in[16];
    const float* Wb_upd   = (const float*)d_in[17];
    const float* bb_upd   = (const float*)d_in[18];
    const float* W_force  = (const float*)d_in[19];
    const float* b_force  = (const float*)d_in[20];
    const float* W_fc1    = (const float*)d_in[21];
    const float* b_fc1    = (const float*)d_in[22];
    const float* W_fc2    = (const float*)d_in[23];
    const float* b_fc2    = (const float*)d_in[24];
    const float* W_fc3    = (const float*)d_in[25];
    const float* b_fc3    = (const float*)d_in[26];
    float* out = (float*)d_out;

    float *pH, *pAgg, *pA1, *pA2;
    __nv_bfloat16 *pWhi, *pWlo, *pHhi, *pHlo;
    cudaGetSymbolAddress((void**)&pH,   g_h);
    cudaGetSymbolAddress((void**)&pAgg, g_agg);
    cudaGetSymbolAddress((void**)&pA1,  g_a1);
    cudaGetSymbolAddress((void**)&pA2,  g_a2);
    cudaGetSymbolAddress((void**)&pWhi, g_wt_hi);
    cudaGetSymbolAddress((void**)&pWlo, g_wt_lo);
    cudaGetSymbolAddress((void**)&pHhi, g_h_hi);
    cudaGetSymbolAddress((void**)&pHlo, g_h_lo);

    cudaFuncSetAttribute(mma_edge_gemm<2>,
                         cudaFuncAttributeMaxDynamicSharedMemorySize, SMB_EDGE);
    cudaFuncSetAttribute(mma_edge_gemm<3>,
                         cudaFuncAttributeMaxDynamicSharedMemorySize, SMB_EDGE);
    cudaFuncSetAttribute(mma_gatemsg,
                         cudaFuncAttributeMaxDynamicSharedMemorySize, SMB_GM);

    // geometry + rbf
    lattice_k<<<1, 256>>>(lengths, angles);
    cart_k<<<NATOMS / 256, 256>>>(frac);
    edge_k<<<NEDGE / 256, 256>>>(src, dst);
    rbf_k<<<NEDGE / 8, 256>>>();

    // weight prep
    wprep_k<<<192, 256>>>(W_edge, pWhi + WOFF_EDGE, pWlo + WOFF_EDGE, 384);
    for (int i = 0; i < 3; i++) {
        wprep_k<<<64, 256>>>(Wb_rbf + (size_t)i * 16384,
                             pWhi + WOFF_RBF + i * 16384, pWlo + WOFF_RBF + i * 16384, 128);
        wprep_k<<<64, 256>>>(Wb_msg + (size_t)i * 16384,
                             pWhi + WOFF_MSG + i * 16384, pWlo + WOFF_MSG + i * 16384, 128);
        wprep_k<<<192, 256>>>(Wb_upd + (size_t)i * 49152,
                              pWhi + WOFF_UPD + i * 49152, pWlo + WOFF_UPD + i * 49152, 384);
    }

    // h = relu(concat(emb, z) @ W_in + b_in)
    gemm_k<1, 384, 1, 1><<<NATOMS / 64, 256>>>(nullptr, W_in, b_in, nullptr, pH,
                                               pHhi, pHlo, emb, z, atype);
    // m = relu(concat(h[src], h[dst], rbf) @ W_edge + b_edge)
    mma_edge_gemm<2><<<NEDGE / 128, 256, SMB_EDGE>>>(
        pWhi + WOFF_EDGE, pWlo + WOFF_EDGE, b_edge, src, dst);

    for (int i = 0; i < 3; i++) {
        zero_agg_k<<<NATOMS * HIDC / 1024, 256>>>();
        // msg = relu(m@Wmsg + b) * (rbf@Wrbf); agg[dst] += msg   (fused)
        mma_gatemsg<<<NEDGE / 128, 256, SMB_GM>>>(
            pWhi + WOFF_RBF + i * 16384, pWlo + WOFF_RBF + i * 16384,
            pWhi + WOFF_MSG + i * 16384, pWlo + WOFF_MSG + i * 16384,
            bb_msg + i * 128, dst);
        // h += relu(agg @ Wb_atom + b)
        gemm_k<0, 128, 3, 1><<<NATOMS / 64, 256>>>(pAgg, Wb_atom + (size_t)i * 16384,
                                                   bb_atom + i * 128, pH, pH,
                                                   pHhi, pHlo, emb, z, atype);
        // m += relu(concat(h[src],h[dst],m) @ Wb_upd + b)
        mma_edge_gemm<3><<<NEDGE / 128, 256, SMB_EDGE>>>(
            pWhi + WOFF_UPD + i * 49152, pWlo + WOFF_UPD + i * 49152,
            bb_upd + i * 128, src, dst);
    }

    force_k<<<NCRYST, 256>>>(W_force, b_force, dst, out);

    gemm_k<0, 128, 1, 0><<<NATOMS / 64, 256>>>(pH, W_fc1, b_fc1, nullptr, pA1,
                                               nullptr, nullptr, emb, z, atype);
    gemm_k<0, 128, 1, 0><<<NATOMS / 64, 256>>>(pA1, W_fc2, b_fc2, nullptr, pA2,
                                               nullptr, nullptr, emb, z, atype);
    fc3_k<<<NATOMS / 8, 256>>>(W_fc3, b_fc3, out + (size_t)NATOMS * 3);

    (void)in_sizes; (void)n_in; (void)out_size;
}

// round 6
// speedup vs baseline: 3.1973x; 1.0063x over previous
#include <cuda_runtime.h>
#include <cuda_bf16.h>
#include <cstdint>

// ---------------------------------------------------------------------------
// GemNetTDecoder — mma.sync bf16x3, pre-split hi/lo storage, cp.async staging.
// R6: rbf never materialized in DRAM — generated on the fly into smem tiles
// (<=13 Gaussian taps per row); saves ~672 MB of traffic + rbf_k.
// ---------------------------------------------------------------------------

#define PI_F 3.14159265358979323846f

constexpr int NCRYST = 256;
constexpr int AA     = 64;
constexpr int KNB    = 20;
constexpr int HIDC   = 128;
constexpr int LATC   = 256;
constexpr int NATOMS = NCRYST * AA;       // 16384
constexpr int NEDGE  = NATOMS * KNB;      // 327680
constexpr float FCUT = 6.0f;
constexpr float DELTA = FCUT / 127.0f;

constexpr size_t EH = (size_t)NEDGE * HIDC;

constexpr int WOFF_EDGE = 0;
constexpr int WOFF_RBF  = 49152;
constexpr int WOFF_MSG  = 98304;
constexpr int WOFF_UPD  = 147456;
constexpr int WTOT      = 294912;

// --------------------------- device scratch -------------------------------
__device__ float g_lat[NCRYST * 9];
__device__ float g_cart[NATOMS * 3];
__device__ float g_dist[NEDGE];
__device__ float g_unit[NEDGE * 3];
__device__ float g_h[NATOMS * HIDC];
__device__ __nv_bfloat16 g_h_hi[NATOMS * HIDC];
__device__ __nv_bfloat16 g_h_lo[NATOMS * HIDC];
__device__ __nv_bfloat16 g_m_hi[EH];
__device__ __nv_bfloat16 g_m_lo[EH];
__device__ float g_agg[NATOMS * HIDC];
__device__ float g_a1[NATOMS * HIDC];
__device__ float g_a2[NATOMS * HIDC];
__device__ __nv_bfloat16 g_wt_hi[WTOT];
__device__ __nv_bfloat16 g_wt_lo[WTOT];

// --------------------------- helpers ---------------------------------------
__device__ __forceinline__ uint32_t smem_u32(const void* p) {
    uint32_t a;
    asm("{ .reg .u64 t; cvta.to.shared.u64 t, %1; cvt.u32.u64 %0, t; }"
        : "=r"(a) : "l"(p));
    return a;
}
__device__ __forceinline__ void ldm4(uint32_t* r, uint32_t a) {
    asm volatile("ldmatrix.sync.aligned.m8n8.x4.shared.b16 {%0,%1,%2,%3}, [%4];"
                 : "=r"(r[0]), "=r"(r[1]), "=r"(r[2]), "=r"(r[3]) : "r"(a));
}
__device__ __forceinline__ void mma16816(float* c, const uint32_t* a,
                                         const uint32_t* b) {
    asm volatile(
        "mma.sync.aligned.m16n8k16.row.col.f32.bf16.bf16.f32 "
        "{%0,%1,%2,%3}, {%4,%5,%6,%7}, {%8,%9}, {%0,%1,%2,%3};"
        : "+f"(c[0]), "+f"(c[1]), "+f"(c[2]), "+f"(c[3])
        : "r"(a[0]), "r"(a[1]), "r"(a[2]), "r"(a[3]), "r"(b[0]), "r"(b[1]));
}
__device__ __forceinline__ void cp16(uint32_t dst, const void* src) {
    asm volatile("cp.async.cg.shared.global [%0], [%1], 16;"
                 :: "r"(dst), "l"(src) : "memory");
}
__device__ __forceinline__ void cp_commit() {
    asm volatile("cp.async.commit_group;" ::: "memory");
}
__device__ __forceinline__ void cp_wait0() {
    asm volatile("cp.async.wait_group 0;" ::: "memory");
}
__device__ __forceinline__ void cp_wait1() {
    asm volatile("cp.async.wait_group 1;" ::: "memory");
}
__device__ __forceinline__ uint32_t pack_bf(__nv_bfloat16 a, __nv_bfloat16 b) {
    return (uint32_t)__bfloat16_as_ushort(a) |
           ((uint32_t)__bfloat16_as_ushort(b) << 16);
}
__device__ __forceinline__ void split2(float v0, float v1, uint32_t& hi,
                                       uint32_t& lo) {
    __nv_bfloat16 h0 = __float2bfloat16(v0), h1 = __float2bfloat16(v1);
    hi = pack_bf(h0, h1);
    lo = pack_bf(__float2bfloat16(v0 - __bfloat162float(h0)),
                 __float2bfloat16(v1 - __bfloat162float(h1)));
}

// smem tile geometry
constexpr int STR   = 72;                 // bf16 per smem row (144 B)
constexpr int TILEB = 128 * STR * 2;      // 18432
constexpr int SA_HI = 0;
constexpr int SA_LO = TILEB;
constexpr int SB_HI = 2 * TILEB;
constexpr int SB_LO = 3 * TILEB;
constexpr int STAGE = 4 * TILEB;          // 73728

// edge gemm: single stage + misc  (2 CTAs/SM)
constexpr int E_BIAS = STAGE;
constexpr int E_SRC  = E_BIAS + 512;
constexpr int E_DST  = E_SRC + 512;
constexpr int E_DIST = E_DST + 512;
constexpr int SMB_EDGE = E_DIST + 512;    // 75776

// gatemsg: two stages + misc (1 CTA/SM); sagg aliases stage 0
constexpr int G_BIAS = 2 * STAGE;         // 147456
constexpr int G_DST  = G_BIAS + 512;
constexpr int G_DIST = G_DST + 512;
constexpr int SMB_GM = G_DIST + 512;      // 148992

// Generate the rbf tile (cols [kc2, kc2+64)) into smem hi/lo planes.
// Requires sdist[128] populated. Caller must __syncthreads() before MMA use.
__device__ __forceinline__ void gen_rbf(char* smp, int off_hi, int off_lo,
                                        const float* sdist, int kc2, int tid) {
    uint4 z4 = make_uint4(0, 0, 0, 0);
#pragma unroll
    for (int i = 0; i < 9; i++) {
        int lin = i * 256 + tid;
        if (lin < 2304) {
            int plane = lin >= 1152;
            int j = plane ? lin - 1152 : lin;
            *(uint4*)(smp + (plane ? off_lo : off_hi) + j * 16) = z4;
        }
    }
    __syncthreads();
    if (tid < 128) {
        float d = sdist[tid];
        if (d < FCUT) {
            float env = 0.5f * (cosf(PI_F * d * (1.f / FCUT)) + 1.f);
            float t = d * (1.f / DELTA);
            int klo = max(kc2, (int)ceilf(t) - 6);
            int khi = min(kc2 + 63, (int)floorf(t) + 6);
            for (int k = klo; k <= khi; k++) {
                float x = t - (float)k;
                float v = __expf(-x * x) * env;
                __nv_bfloat16 h = __float2bfloat16(v);
                __nv_bfloat16 l = __float2bfloat16(v - __bfloat162float(h));
                int boff = tid * 144 + (k - kc2) * 2;
                *(__nv_bfloat16*)(smp + off_hi + boff) = h;
                *(__nv_bfloat16*)(smp + off_lo + boff) = l;
            }
        }
    }
}

// --------------------------- small kernels --------------------------------
__global__ void lattice_k(const float* __restrict__ lengths,
                          const float* __restrict__ angles) {
    int i = threadIdx.x;
    if (i >= NCRYST) return;
    float r0 = angles[i * 3 + 0] * (PI_F / 180.f);
    float r1 = angles[i * 3 + 1] * (PI_F / 180.f);
    float r2 = angles[i * 3 + 2] * (PI_F / 180.f);
    float c0 = cosf(r0), c1 = cosf(r1), c2 = cosf(r2), sg = sinf(r2);
    float a = lengths[i * 3 + 0], b = lengths[i * 3 + 1], c = lengths[i * 3 + 2];
    float cx = c * c1;
    float cy = c * (c0 - c1 * c2) / sg;
    float cz = sqrtf(fmaxf(c * c - cx * cx - cy * cy, 1e-8f));
    float* L = &g_lat[i * 9];
    L[0] = a;      L[1] = 0.f;    L[2] = 0.f;
    L[3] = b * c2; L[4] = b * sg; L[5] = 0.f;
    L[6] = cx;     L[7] = cy;     L[8] = cz;
}

__global__ void cart_k(const float* __restrict__ frac) {
    int i = blockIdx.x * blockDim.x + threadIdx.x;
    if (i >= NATOMS) return;
    const float* L = &g_lat[(i >> 6) * 9];
    float f0 = frac[i * 3 + 0], f1 = frac[i * 3 + 1], f2 = frac[i * 3 + 2];
    g_cart[i * 3 + 0] = f0 * L[0] + f1 * L[3] + f2 * L[6];
    g_cart[i * 3 + 1] = f0 * L[1] + f1 * L[4] + f2 * L[7];
    g_cart[i * 3 + 2] = f0 * L[2] + f1 * L[5] + f2 * L[8];
}

__global__ void edge_k(const int* __restrict__ src, const int* __restrict__ dst) {
    int e = blockIdx.x * blockDim.x + threadIdx.x;
    if (e >= NEDGE) return;
    int s = src[e], d = dst[e];
    float dx = g_cart[d * 3 + 0] - g_cart[s * 3 + 0];
    float dy = g_cart[d * 3 + 1] - g_cart[s * 3 + 1];
    float dz = g_cart[d * 3 + 2] - g_cart[s * 3 + 2];
    float dist = sqrtf(dx * dx + dy * dy + dz * dz + 1e-12f);
    g_dist[e] = dist;
    float inv = 1.f / dist;
    g_unit[e * 3 + 0] = dx * inv;
    g_unit[e * 3 + 1] = dy * inv;
    g_unit[e * 3 + 2] = dz * inv;
}

__global__ void wprep_k(const float* __restrict__ W, __nv_bfloat16* __restrict__ hi,
                        __nv_bfloat16* __restrict__ lo, int K) {
    int idx = blockIdx.x * 256 + threadIdx.x;
    if (idx >= K * 128) return;
    int k = idx >> 7, n = idx & 127;
    float v = W[idx];
    __nv_bfloat16 h = __float2bfloat16(v);
    hi[n * K + k] = h;
    lo[n * K + k] = __float2bfloat16(v - __bfloat162float(h));
}

__global__ void zero_agg_k() {
    int i = blockIdx.x * 256 + threadIdx.x;
    *(float4*)&g_agg[(size_t)i * 4] = make_float4(0.f, 0.f, 0.f, 0.f);
}

// --------------------------- fp32 SIMT gemm (small) ------------------------
template <int MODE, int KDIM, int EPI, int SPLIT>
__global__ __launch_bounds__(256) void gemm_k(
    const float* __restrict__ X, const float* __restrict__ W,
    const float* __restrict__ bias, const float* __restrict__ base,
    float* __restrict__ out, __nv_bfloat16* __restrict__ outhi,
    __nv_bfloat16* __restrict__ outlo, const float* __restrict__ emb,
    const float* __restrict__ z, const int* __restrict__ atype) {
    __shared__ float Xs[16][68];
    __shared__ float Ws[16][128];
    __shared__ int sat[64];

    int row0 = blockIdx.x * 64;
    int tid = threadIdx.x;
    if (MODE == 1) {
        if (tid < 64) sat[tid] = atype[row0 + tid];
        __syncthreads();
    }

    int c0 = (tid & 15) * 8;
    int r0 = (tid >> 4) * 4;
    float acc[4][8];
#pragma unroll
    for (int i = 0; i < 4; i++)
#pragma unroll
        for (int j = 0; j < 8; j++) acc[i][j] = 0.f;

    for (int k0 = 0; k0 < KDIM; k0 += 16) {
#pragma unroll
        for (int t = 0; t < 4; t++) {
            int lin = tid * 4 + t;
            int r = lin >> 4, kk = lin & 15;
            int k = k0 + kk;
            float v;
            if (MODE == 0) {
                v = X[(size_t)(row0 + r) * KDIM + k];
            } else {
                v = (k < 128) ? emb[sat[r] * 128 + k]
                              : z[(size_t)((row0 + r) >> 6) * LATC + (k - 128)];
            }
            Xs[kk][r] = v;
        }
#pragma unroll
        for (int t = 0; t < 2; t++) {
            int i4 = tid + t * 256;
            int kk = i4 >> 5, n = (i4 & 31) * 4;
            *(float4*)&Ws[kk][n] = *(const float4*)&W[(size_t)(k0 + kk) * 128 + n];
        }
        __syncthreads();
#pragma unroll
        for (int kk = 0; kk < 16; kk++) {
            float4 a  = *(const float4*)&Xs[kk][r0];
            float4 b0 = *(const float4*)&Ws[kk][c0];
            float4 b1 = *(const float4*)&Ws[kk][c0 + 4];
            float av[4] = {a.x, a.y, a.z, a.w};
            float bv[8] = {b0.x, b0.y, b0.z, b0.w, b1.x, b1.y, b1.z, b1.w};
#pragma unroll
            for (int i = 0; i < 4; i++)
#pragma unroll
                for (int j = 0; j < 8; j++) acc[i][j] += av[i] * bv[j];
        }
        __syncthreads();
    }

    float bv[8];
    {
        float4 q0 = *(const float4*)&bias[c0];
        float4 q1 = *(const float4*)&bias[c0 + 4];
        bv[0] = q0.x; bv[1] = q0.y; bv[2] = q0.z; bv[3] = q0.w;
        bv[4] = q1.x; bv[5] = q1.y; bv[6] = q1.z; bv[7] = q1.w;
    }
#pragma unroll
    for (int i = 0; i < 4; i++) {
        size_t off = (size_t)(row0 + r0 + i) * 128 + c0;
        float v[8];
#pragma unroll
        for (int j = 0; j < 8; j++) v[j] = fmaxf(acc[i][j] + bv[j], 0.f);
        if (EPI == 3) {
            float4 bb0 = *(const float4*)&base[off];
            float4 bb1 = *(const float4*)&base[off + 4];
            v[0] += bb0.x; v[1] += bb0.y; v[2] += bb0.z; v[3] += bb0.w;
            v[4] += bb1.x; v[5] += bb1.y; v[6] += bb1.z; v[7] += bb1.w;
        }
        float4 o0 = {v[0], v[1], v[2], v[3]};
        float4 o1 = {v[4], v[5], v[6], v[7]};
        *(float4*)&out[off] = o0;
        *(float4*)&out[off + 4] = o1;
        if (SPLIT) {
            uint32_t hh[4], ll[4];
#pragma unroll
            for (int q = 0; q < 4; q++) split2(v[2 * q], v[2 * q + 1], hh[q], ll[q]);
            *(uint4*)&outhi[off] = make_uint4(hh[0], hh[1], hh[2], hh[3]);
            *(uint4*)&outlo[off] = make_uint4(ll[0], ll[1], ll[2], ll[3]);
        }
    }
}

// --------------------------- mma.sync edge GEMM ----------------------------
// MODE 2: TAIL = rbf (generated in smem), m = relu(acc+bias)
// MODE 3: TAIL = m,   m += relu(acc+bias)
// Single-stage staging, 2 CTAs/SM.
template <int MODE>
__global__ __launch_bounds__(256, 2) void mma_edge_gemm(
    const __nv_bfloat16* __restrict__ wt_hi, const __nv_bfloat16* __restrict__ wt_lo,
    const float* __restrict__ bias, const int* __restrict__ srcp,
    const int* __restrict__ dstp) {
    extern __shared__ char sm[];
    uint32_t sbase = smem_u32(sm);
    float* sbias = (float*)(sm + E_BIAS);
    int* ssrc = (int*)(sm + E_SRC);
    int* sdst = (int*)(sm + E_DST);
    float* sdist = (float*)(sm + E_DIST);

    int tid = threadIdx.x;
    int row0 = blockIdx.x * 128;
    if (tid < 128) {
        ssrc[tid] = srcp[row0 + tid];
        sdst[tid] = dstp[row0 + tid];
        sbias[tid] = bias[tid];
        if (MODE == 2) sdist[tid] = g_dist[row0 + tid];
    }
    __syncthreads();

    auto prefetch = [&](int c) {
        int kc = c * 64;
        bool gen_a = (MODE == 2 && c >= 4);
#pragma unroll
        for (int i = 0; i < 8; i++) {
            int lin = i * 256 + tid;
            int plane = lin >> 10;
            int idx = lin & 1023;
            int row = idx >> 3;
            int seg = idx & 7;
            if (!gen_a) {
                const __nv_bfloat16* ap;
                if (c >= 4) {
                    ap = (plane ? g_m_lo : g_m_hi) +
                         (size_t)(row0 + row) * 128 + (kc - 256) + seg * 8;
                } else if (c < 2) {
                    ap = (plane ? g_h_lo : g_h_hi) + (size_t)ssrc[row] * 128 + kc + seg * 8;
                } else {
                    ap = (plane ? g_h_lo : g_h_hi) + (size_t)sdst[row] * 128 +
                         (kc - 128) + seg * 8;
                }
                cp16(sbase + (plane ? SA_LO : SA_HI) + row * 144 + seg * 16, ap);
            }
            const __nv_bfloat16* bp =
                (plane ? wt_lo : wt_hi) + (size_t)row * 384 + kc + seg * 8;
            cp16(sbase + (plane ? SB_LO : SB_HI) + row * 144 + seg * 16, bp);
        }
        cp_commit();
    };

    int lane = tid & 31;
    int wm = (tid >> 5) & 3;
    int wn = tid >> 7;
    uint32_t a_row_l = (lane & 7) + ((lane >> 3) & 1) * 8;
    uint32_t a_k_l   = (lane >> 4) * 8;
    uint32_t b_n_l   = (lane & 7) + ((lane >> 4) & 1) * 8;
    uint32_t b_k_l   = ((lane >> 3) & 1) * 8;

    float acc[2][8][4];
#pragma unroll
    for (int i = 0; i < 2; i++)
#pragma unroll
        for (int j = 0; j < 8; j++)
#pragma unroll
            for (int q = 0; q < 4; q++) acc[i][j][q] = 0.f;

    for (int c = 0; c < 6; c++) {
        prefetch(c);
        if (MODE == 2 && c >= 4)
            gen_rbf(sm, SA_HI, SA_LO, sdist, (c - 4) * 64, tid);
        cp_wait0();
        __syncthreads();
#pragma unroll
        for (int k16 = 0; k16 < 4; k16++) {
            uint32_t kk = k16 * 16;
            uint32_t ah[2][4], al[2][4];
#pragma unroll
            for (int mi = 0; mi < 2; mi++) {
                uint32_t off = (((uint32_t)(wm * 32 + mi * 16) + a_row_l) * STR +
                                kk + a_k_l) * 2;
                ldm4(ah[mi], sbase + SA_HI + off);
                ldm4(al[mi], sbase + SA_LO + off);
            }
#pragma unroll
            for (int p = 0; p < 4; p++) {
                uint32_t off = (((uint32_t)(wn * 64 + p * 16) + b_n_l) * STR +
                                kk + b_k_l) * 2;
                uint32_t r4[4], s4[4];
                ldm4(r4, sbase + SB_HI + off);
                ldm4(s4, sbase + SB_LO + off);
#pragma unroll
                for (int mi = 0; mi < 2; mi++) {
                    mma16816(acc[mi][2 * p],     ah[mi], &r4[0]);
                    mma16816(acc[mi][2 * p + 1], ah[mi], &r4[2]);
                    mma16816(acc[mi][2 * p],     ah[mi], &s4[0]);
                    mma16816(acc[mi][2 * p + 1], ah[mi], &s4[2]);
                    mma16816(acc[mi][2 * p],     al[mi], &r4[0]);
                    mma16816(acc[mi][2 * p + 1], al[mi], &r4[2]);
                }
            }
        }
        __syncthreads();
    }

    // epilogue: write m hi/lo planes (residual read hits L2 for MODE 3)
    int r_base = row0 + wm * 32 + (lane >> 2);
    int c_base = wn * 64 + (lane & 3) * 2;
#pragma unroll
    for (int mi = 0; mi < 2; mi++)
#pragma unroll
        for (int nj = 0; nj < 8; nj++) {
            int row = r_base + mi * 16;
            int col = c_base + nj * 8;
            float2 bb = *(const float2*)&sbias[col];
#pragma unroll
            for (int half = 0; half < 2; half++) {
                size_t off = (size_t)(row + half * 8) * 128 + col;
                float v0 = fmaxf(acc[mi][nj][half * 2 + 0] + bb.x, 0.f);
                float v1 = fmaxf(acc[mi][nj][half * 2 + 1] + bb.y, 0.f);
                if (MODE == 3) {
                    uint32_t oh = *(const uint32_t*)&g_m_hi[off];
                    uint32_t ol = *(const uint32_t*)&g_m_lo[off];
                    v0 += __bfloat162float(__ushort_as_bfloat16(oh & 0xffff)) +
                          __bfloat162float(__ushort_as_bfloat16(ol & 0xffff));
                    v1 += __bfloat162float(__ushort_as_bfloat16(oh >> 16)) +
                          __bfloat162float(__ushort_as_bfloat16(ol >> 16));
                }
                uint32_t hh, ll;
                split2(v0, v1, hh, ll);
                *(uint32_t*)&g_m_hi[off] = hh;
                *(uint32_t*)&g_m_lo[off] = ll;
            }
        }
}

// --------------------------- fused gate*msg + segment-sum ------------------
// gate = rbf @ Wrbf (rbf generated in smem) ; msg = relu(m @ Wmsg + b) * gate;
// agg[dst] += msg   (smem reduction + global atomics)
__global__ __launch_bounds__(256) void mma_gatemsg(
    const __nv_bfloat16* __restrict__ wrbf_hi, const __nv_bfloat16* __restrict__ wrbf_lo,
    const __nv_bfloat16* __restrict__ wmsg_hi, const __nv_bfloat16* __restrict__ wmsg_lo,
    const float* __restrict__ bias, const int* __restrict__ dstp) {
    extern __shared__ char sm[];
    uint32_t sbase = smem_u32(sm);
    float* sbias = (float*)(sm + G_BIAS);
    int* sdst = (int*)(sm + G_DST);
    float* sdist = (float*)(sm + G_DIST);

    int tid = threadIdx.x;
    int row0 = blockIdx.x * 128;
    if (tid < 128) {
        sbias[tid] = bias[tid];
        sdst[tid] = dstp[row0 + tid] & 63;
        sdist[tid] = g_dist[row0 + tid];
    }
    __syncthreads();

    auto prefetch = [&](int c, int s) {
        bool is_gate = (c < 2);
        int kc = (c & 1) * 64;
        uint32_t st = sbase + s * STAGE;
        const __nv_bfloat16* whi = is_gate ? wrbf_hi : wmsg_hi;
        const __nv_bfloat16* wlo = is_gate ? wrbf_lo : wmsg_lo;
#pragma unroll
        for (int i = 0; i < 8; i++) {
            int lin = i * 256 + tid;
            int plane = lin >> 10;
            int idx = lin & 1023;
            int row = idx >> 3;
            int seg = idx & 7;
            if (!is_gate) {
                const __nv_bfloat16* ap =
                    (plane ? g_m_lo : g_m_hi) + (size_t)(row0 + row) * 128 + kc + seg * 8;
                cp16(st + (plane ? SA_LO : SA_HI) + row * 144 + seg * 16, ap);
            }
            const __nv_bfloat16* bp =
                (plane ? wlo : whi) + (size_t)row * 128 + kc + seg * 8;
            cp16(st + (plane ? SB_LO : SB_HI) + row * 144 + seg * 16, bp);
        }
        cp_commit();
    };

    int lane = tid & 31;
    int wm = (tid >> 5) & 3;
    int wn = tid >> 7;
    uint32_t a_row_l = (lane & 7) + ((lane >> 3) & 1) * 8;
    uint32_t a_k_l   = (lane >> 4) * 8;
    uint32_t b_n_l   = (lane & 7) + ((lane >> 4) & 1) * 8;
    uint32_t b_k_l   = ((lane >> 3) & 1) * 8;

    float accg[2][8][4], accm[2][8][4];
#pragma unroll
    for (int i = 0; i < 2; i++)
#pragma unroll
        for (int j = 0; j < 8; j++)
#pragma unroll
            for (int q = 0; q < 4; q++) { accg[i][j][q] = 0.f; accm[i][j][q] = 0.f; }

    prefetch(0, 0);
    gen_rbf(sm, SA_HI, SA_LO, sdist, 0, tid);
    prefetch(1, 1);
    gen_rbf(sm + STAGE, SA_HI, SA_LO, sdist, 64, tid);

    for (int c = 0; c < 4; c++) {
        bool is_gate = (c < 2);
        if (c + 1 < 4) cp_wait1(); else cp_wait0();
        __syncthreads();
        uint32_t st = sbase + (c & 1) * STAGE;
#pragma unroll
        for (int k16 = 0; k16 < 4; k16++) {
            uint32_t kk = k16 * 16;
            uint32_t ah[2][4], al[2][4];
#pragma unroll
            for (int mi = 0; mi < 2; mi++) {
                uint32_t off = (((uint32_t)(wm * 32 + mi * 16) + a_row_l) * STR +
                                kk + a_k_l) * 2;
                ldm4(ah[mi], st + SA_HI + off);
                ldm4(al[mi], st + SA_LO + off);
            }
#pragma unroll
            for (int p = 0; p < 4; p++) {
                uint32_t off = (((uint32_t)(wn * 64 + p * 16) + b_n_l) * STR +
                                kk + b_k_l) * 2;
                uint32_t r4[4], s4[4];
                ldm4(r4, st + SB_HI + off);
                ldm4(s4, st + SB_LO + off);
#pragma unroll
                for (int mi = 0; mi < 2; mi++) {
                    float* a0 = is_gate ? accg[mi][2 * p] : accm[mi][2 * p];
                    float* a1 = is_gate ? accg[mi][2 * p + 1] : accm[mi][2 * p + 1];
                    mma16816(a0, ah[mi], &r4[0]);
                    mma16816(a1, ah[mi], &r4[2]);
                    mma16816(a0, ah[mi], &s4[0]);
                    mma16816(a1, ah[mi], &s4[2]);
                    mma16816(a0, al[mi], &r4[0]);
                    mma16816(a1, al[mi], &r4[2]);
                }
            }
        }
        __syncthreads();
        if (c + 2 < 4) prefetch(c + 2, c & 1);
    }

    // fused epilogue: msg -> smem sagg (64 atoms x 128 cols) -> g_agg
    float* sagg = (float*)sm;   // alias stage buffers
    for (int i = tid; i < AA * HIDC; i += 256) sagg[i] = 0.f;
    __syncthreads();

    int rl_base = wm * 32 + (lane >> 2);
    int c_base = wn * 64 + (lane & 3) * 2;
#pragma unroll
    for (int mi = 0; mi < 2; mi++)
#pragma unroll
        for (int half = 0; half < 2; half++) {
            int rl = rl_base + mi * 16 + half * 8;
            int ld = sdst[rl];
#pragma unroll
            for (int nj = 0; nj < 8; nj++) {
                int col = c_base + nj * 8;
                float v0 = fmaxf(accm[mi][nj][half * 2 + 0] + sbias[col], 0.f) *
                           accg[mi][nj][half * 2 + 0];
                float v1 = fmaxf(accm[mi][nj][half * 2 + 1] + sbias[col + 1], 0.f) *
                           accg[mi][nj][half * 2 + 1];
                atomicAdd(&sagg[ld * 128 + col], v0);
                atomicAdd(&sagg[ld * 128 + col + 1], v1);
            }
        }
    __syncthreads();

    size_t base = (size_t)(row0 / (AA * KNB)) * AA * HIDC;
    for (int i = tid; i < AA * HIDC; i += 256)
        atomicAdd(&g_agg[base + i], sagg[i]);
}

// --------------------------- force / fc3 -----------------------------------
__global__ __launch_bounds__(256) void force_k(const float* __restrict__ Wf,
                                               const float* __restrict__ bf,
                                               const int* __restrict__ dst,
                                               float* __restrict__ out) {
    __shared__ float sW[128];
    __shared__ float sacc[AA * 3];
    int c = blockIdx.x, tid = threadIdx.x;
    if (tid < 128) sW[tid] = Wf[tid];
    if (tid < AA * 3) sacc[tid] = 0.f;
    __syncthreads();
    int w = tid >> 5, lane = tid & 31;
    float b0 = bf[0];
    for (int el = w; el < AA * KNB; el += 8) {
        int e = c * AA * KNB + el;
        size_t base = (size_t)e * 128;
        float p = 0.f;
#pragma unroll
        for (int k = lane; k < 128; k += 32) {
            float v = __bfloat162float(g_m_hi[base + k]) +
                      __bfloat162float(g_m_lo[base + k]);
            p += v * sW[k];
        }
#pragma unroll
        for (int o = 16; o; o >>= 1) p += __shfl_xor_sync(0xffffffffu, p, o);
        float f = p + b0;
        int ld = dst[e] - (c << 6);
        if (lane < 3) atomicAdd(&sacc[ld * 3 + lane], f * g_unit[e * 3 + lane]);
    }
    __syncthreads();
    if (tid < AA * 3) out[(size_t)c * AA * 3 + tid] = sacc[tid];
}

__global__ __launch_bounds__(256) void fc3_k(const float* __restrict__ W,
                                             const float* __restrict__ b,
                                             float* __restrict__ out) {
    int atom = blockIdx.x * 8 + (threadIdx.x >> 5);
    int lane = threadIdx.x & 31;
    const float* ar = &g_a2[(size_t)atom * 128];
    float p0 = 0.f, p1 = 0.f;
#pragma unroll
    for (int k = lane; k < 128; k += 32) {
        float v = ar[k];
        p0 += v * W[k * 2 + 0];
        p1 += v * W[k * 2 + 1];
    }
#pragma unroll
    for (int o = 16; o; o >>= 1) {
        p0 += __shfl_xor_sync(0xffffffffu, p0, o);
        p1 += __shfl_xor_sync(0xffffffffu, p1, o);
    }
    if (lane == 0) {
        out[atom * 2 + 0] = p0 + b[0];
        out[atom * 2 + 1] = p1 + b[1];
    }
}

// ---------------------------------------------------------------------------
extern "C" void kernel_launch(void* const* d_in, const int* in_sizes, int n_in,
                              void* d_out, int out_size) {
    const float* z        = (const float*)d_in[0];
    const float* frac     = (const float*)d_in[1];
    const float* lengths  = (const float*)d_in[2];
    const float* angles   = (const float*)d_in[3];
    const int*   atype    = (const int*)d_in[4];
    const int*   src      = (const int*)d_in[5];
    const int*   dst      = (const int*)d_in[6];
    const float* emb      = (const float*)d_in[7];
    const float* W_in     = (const float*)d_in[8];
    const float* b_in     = (const float*)d_in[9];
    const float* W_edge   = (const float*)d_in[10];
    const float* b_edge   = (const float*)d_in[11];
    const float* Wb_rbf   = (const float*)d_in[12];
    const float* Wb_msg   = (const float*)d_in[13];
    const float* bb_msg   = (const float*)d_in[14];
    const float* Wb_atom  = (const float*)d_in[15];
    const float* bb_atom  = (const float*)d_in[16];
    const float* Wb_upd   = (const float*)d_in[17];
    const float* bb_upd   = (const float*)d_in[18];
    const float* W_force  = (const float*)d_in[19];
    const float* b_force  = (const float*)d_in[20];
    const float* W_fc1    = (const float*)d_in[21];
    const float* b_fc1    = (const float*)d_in[22];
    const float* W_fc2    = (const float*)d_in[23];
    const float* b_fc2    = (const float*)d_in[24];
    const float* W_fc3    = (const float*)d_in[25];
    const float* b_fc3    = (const float*)d_in[26];
    float* out = (float*)d_out;

    float *pH, *pAgg, *pA1, *pA2;
    __nv_bfloat16 *pWhi, *pWlo, *pHhi, *pHlo;
    cudaGetSymbolAddress((void**)&pH,   g_h);
    cudaGetSymbolAddress((void**)&pAgg, g_agg);
    cudaGetSymbolAddress((void**)&pA1,  g_a1);
    cudaGetSymbolAddress((void**)&pA2,  g_a2);
    cudaGetSymbolAddress((void**)&pWhi, g_wt_hi);
    cudaGetSymbolAddress((void**)&pWlo, g_wt_lo);
    cudaGetSymbolAddress((void**)&pHhi, g_h_hi);
    cudaGetSymbolAddress((void**)&pHlo, g_h_lo);

    cudaFuncSetAttribute(mma_edge_gemm<2>,
                         cudaFuncAttributeMaxDynamicSharedMemorySize, SMB_EDGE);
    cudaFuncSetAttribute(mma_edge_gemm<3>,
                         cudaFuncAttributeMaxDynamicSharedMemorySize, SMB_EDGE);
    cudaFuncSetAttribute(mma_gatemsg,
                         cudaFuncAttributeMaxDynamicSharedMemorySize, SMB_GM);

    // geometry
    lattice_k<<<1, 256>>>(lengths, angles);
    cart_k<<<NATOMS / 256, 256>>>(frac);
    edge_k<<<NEDGE / 256, 256>>>(src, dst);

    // weight prep
    wprep_k<<<192, 256>>>(W_edge, pWhi + WOFF_EDGE, pWlo + WOFF_EDGE, 384);
    for (int i = 0; i < 3; i++) {
        wprep_k<<<64, 256>>>(Wb_rbf + (size_t)i * 16384,
                             pWhi + WOFF_RBF + i * 16384, pWlo + WOFF_RBF + i * 16384, 128);
        wprep_k<<<64, 256>>>(Wb_msg + (size_t)i * 16384,
                             pWhi + WOFF_MSG + i * 16384, pWlo + WOFF_MSG + i * 16384, 128);
        wprep_k<<<192, 256>>>(Wb_upd + (size_t)i * 49152,
                              pWhi + WOFF_UPD + i * 49152, pWlo + WOFF_UPD + i * 49152, 384);
    }

    // h = relu(concat(emb, z) @ W_in + b_in)
    gemm_k<1, 384, 1, 1><<<NATOMS / 64, 256>>>(nullptr, W_in, b_in, nullptr, pH,
                                               pHhi, pHlo, emb, z, atype);
    // m = relu(concat(h[src], h[dst], rbf) @ W_edge + b_edge)
    mma_edge_gemm<2><<<NEDGE / 128, 256, SMB_EDGE>>>(
        pWhi + WOFF_EDGE, pWlo + WOFF_EDGE, b_edge, src, dst);

    for (int i = 0; i < 3; i++) {
        zero_agg_k<<<NATOMS * HIDC / 1024, 256>>>();
        mma_gatemsg<<<NEDGE / 128, 256, SMB_GM>>>(
            pWhi + WOFF_RBF + i * 16384, pWlo + WOFF_RBF + i * 16384,
            pWhi + WOFF_MSG + i * 16384, pWlo + WOFF_MSG + i * 16384,
            bb_msg + i * 128, dst);
        gemm_k<0, 128, 3, 1><<<NATOMS / 64, 256>>>(pAgg, Wb_atom + (size_t)i * 16384,
                                                   bb_atom + i * 128, pH, pH,
                                                   pHhi, pHlo, emb, z, atype);
        mma_edge_gemm<3><<<NEDGE / 128, 256, SMB_EDGE>>>(
            pWhi + WOFF_UPD + i * 49152, pWlo + WOFF_UPD + i * 49152,
            bb_upd + i * 128, src, dst);
    }

    force_k<<<NCRYST, 256>>>(W_force, b_force, dst, out);

    gemm_k<0, 128, 1, 0><<<NATOMS / 64, 256>>>(pH, W_fc1, b_fc1, nullptr, pA1,
                                               nullptr, nullptr, emb, z, atype);
    gemm_k<0, 128, 1, 0><<<NATOMS / 64, 256>>>(pA1, W_fc2, b_fc2, nullptr, pA2,
                                               nullptr, nullptr, emb, z, atype);
    fc3_k<<<NATOMS / 8, 256>>>(W_fc3, b_fc3, out + (size_t)NATOMS * 3);

    (void)in_sizes; (void)n_in; (void)out_size;
}